// round 1
// baseline (speedup 1.0000x reference)
#include <cuda_runtime.h>
#include <cstdint>
#include <cstddef>

#define CDIM 1024
#define HEADS 16
#define DHD 64
#define LSEQ 2048
#define BATCH 2
#define DFF 4096
#define NROWS (BATCH*LSEQ)   /* 4096 */

// ---------------- scratch (device globals: alloc-free) ----------------
__device__ float g_ada[BATCH * 6 * CDIM];                 // [B,6,C]
__device__ float g_h[(size_t)NROWS * CDIM];               // LN-mod output
__device__ float g_qkv[(size_t)NROWS * 3 * CDIM];         // [B*L, 3, H, DH]
__device__ float g_attn[(size_t)NROWS * CDIM];            // attention out [B*L, C]
__device__ float g_x1[(size_t)NROWS * CDIM];              // x after attn residual
__device__ float g_ff[(size_t)NROWS * DFF];               // fc1 output

// ---------------- ada = silu(cond) @ ada_w.T + ada_b ----------------
__global__ __launch_bounds__(128) void ada_kernel(
    const float* __restrict__ cond, const float* __restrict__ ada_w,
    const float* __restrict__ ada_b)
{
    const int warp = threadIdx.x >> 5;
    const int lane = threadIdx.x & 31;
    const int o = blockIdx.x * 4 + warp;           // 0..6143
    const int b = blockIdx.y;
    const float* wr = ada_w + (size_t)o * CDIM;
    const float* cr = cond + b * CDIM;
    float s = 0.f;
    for (int k = lane; k < CDIM; k += 32) {
        float c = cr[k];
        float si = c / (1.f + expf(-c));
        s += si * wr[k];
    }
    #pragma unroll
    for (int m = 16; m; m >>= 1) s += __shfl_xor_sync(0xffffffffu, s, m);
    if (lane == 0) g_ada[b * 6 * CDIM + o] = s + ada_b[o];
}

// ---------------- h = LN(x) * (scale+1) + shift ----------------
__global__ __launch_bounds__(256) void ln_mod_kernel(
    const float* __restrict__ x, float* __restrict__ h, int sc, int sh)
{
    __shared__ float red[18];
    const int row = blockIdx.x;
    const int b = row >> 11;  // row / LSEQ
    const float* xr = x + (size_t)row * CDIM;
    float v[4];
    float s = 0.f, ss = 0.f;
    #pragma unroll
    for (int u = 0; u < 4; u++) {
        v[u] = xr[threadIdx.x + u * 256];
        s += v[u]; ss += v[u] * v[u];
    }
    #pragma unroll
    for (int m = 16; m; m >>= 1) {
        s  += __shfl_xor_sync(0xffffffffu, s, m);
        ss += __shfl_xor_sync(0xffffffffu, ss, m);
    }
    __shared__ float ws[16];
    int w = threadIdx.x >> 5, ln = threadIdx.x & 31;
    if (ln == 0) { ws[w] = s; ws[8 + w] = ss; }
    __syncthreads();
    if (threadIdx.x == 0) {
        float S = 0.f, SS = 0.f;
        #pragma unroll
        for (int i = 0; i < 8; i++) { S += ws[i]; SS += ws[8 + i]; }
        float m = S * (1.f / CDIM);
        float var = SS * (1.f / CDIM) - m * m;
        red[16] = m;
        red[17] = rsqrtf(var + 1e-6f);
    }
    __syncthreads();
    const float mean = red[16], rstd = red[17];
    const float* ap = g_ada + b * 6 * CDIM;
    #pragma unroll
    for (int u = 0; u < 4; u++) {
        int c = threadIdx.x + u * 256;
        h[(size_t)row * CDIM + c] =
            (v[u] - mean) * rstd * (ap[sc * CDIM + c] + 1.f) + ap[sh * CDIM + c];
    }
}

// ---------------- SGEMM: C[M,N] = A[M,K] @ W[N,K]^T (+bias)(gelu)(gate)(res) ----------------
// 128x128 tile, BK=8, 8x8 per thread, 256 threads.
__global__ __launch_bounds__(256) void sgemm_kernel(
    int M, int N, int K,
    const float* __restrict__ A, const float* __restrict__ W,
    const float* __restrict__ bias, float* __restrict__ C,
    const float* __restrict__ res, int gate_chunk, int act)
{
    __shared__ float As[8][128];
    __shared__ float Bs[8][128];
    const int tid = threadIdx.x;
    const int bx = blockIdx.x, by = blockIdx.y;
    const int tx = tid & 15, ty = tid >> 4;
    const int rA = tid >> 1;             // 0..127
    const int cA = (tid & 1) * 4;        // 0 or 4
    const float* Ag = A + (size_t)(by * 128 + rA) * K;
    const float* Wg = W + (size_t)(bx * 128 + rA) * K;
    float acc[8][8] = {};
    for (int k0 = 0; k0 < K; k0 += 8) {
        float4 av = *(const float4*)(Ag + k0 + cA);
        float4 wv = *(const float4*)(Wg + k0 + cA);
        As[cA + 0][rA] = av.x; As[cA + 1][rA] = av.y;
        As[cA + 2][rA] = av.z; As[cA + 3][rA] = av.w;
        Bs[cA + 0][rA] = wv.x; Bs[cA + 1][rA] = wv.y;
        Bs[cA + 2][rA] = wv.z; Bs[cA + 3][rA] = wv.w;
        __syncthreads();
        #pragma unroll
        for (int k = 0; k < 8; k++) {
            float a[8], b[8];
            #pragma unroll
            for (int i = 0; i < 8; i++) a[i] = As[k][ty * 8 + i];
            #pragma unroll
            for (int j = 0; j < 8; j++) b[j] = Bs[k][tx * 8 + j];
            #pragma unroll
            for (int i = 0; i < 8; i++)
                #pragma unroll
                for (int j = 0; j < 8; j++)
                    acc[i][j] += a[i] * b[j];
        }
        __syncthreads();
    }
    #pragma unroll
    for (int i = 0; i < 8; i++) {
        int m = by * 128 + ty * 8 + i;
        int bb = m >> 11;  // m / LSEQ
        #pragma unroll
        for (int j = 0; j < 8; j++) {
            int n = bx * 128 + tx * 8 + j;
            float v = acc[i][j];
            if (bias) v += bias[n];
            if (act == 1) {  // gelu tanh
                float v3 = v * v * v;
                v = 0.5f * v * (1.f + tanhf(0.7978845608028654f * (v + 0.044715f * v3)));
            }
            if (gate_chunk >= 0) v *= g_ada[bb * 6 * CDIM + gate_chunk * CDIM + n];
            if (res) v += res[(size_t)m * N + n];
            C[(size_t)m * N + n] = v;
        }
    }
}

// ---------------- qkv: add biases, L2-normalize q/k, q *= exp(min(scale_mul,log100)) ----------------
__global__ __launch_bounds__(256) void qkv_norm_kernel(
    const float* __restrict__ q_bias, const float* __restrict__ v_bias,
    const float* __restrict__ scale_mul)
{
    const int gw = blockIdx.x * 8 + (threadIdx.x >> 5);
    const int lane = threadIdx.x & 31;
    const int h = gw & 15;
    const int t = (gw >> 4) % 3;
    const int bl = gw / 48;            // 0..4095
    float* p = g_qkv + ((size_t)bl * 3 + t) * CDIM + h * DHD;
    float v0 = p[lane], v1 = p[lane + 32];
    if (t == 0) { v0 += q_bias[h * DHD + lane]; v1 += q_bias[h * DHD + lane + 32]; }
    else if (t == 2) { v0 += v_bias[h * DHD + lane]; v1 += v_bias[h * DHD + lane + 32]; }
    if (t < 2) {
        float ss = v0 * v0 + v1 * v1;
        #pragma unroll
        for (int m = 16; m; m >>= 1) ss += __shfl_xor_sync(0xffffffffu, ss, m);
        float r = rsqrtf(fmaxf(ss, 1e-24f));
        if (t == 0) r *= expf(fminf(scale_mul[h], 4.605170185988092f));
        v0 *= r; v1 *= r;
    }
    p[lane] = v0; p[lane + 32] = v1;
}

// ---------------- flash attention: per (b,h), 64-query tiles, online softmax ----------------
__global__ __launch_bounds__(256) void flash_kernel(
    const float* __restrict__ abias, float* __restrict__ out)
{
    __shared__ float sQT[DHD][64];   // [d][r]  (d-major)
    __shared__ float sKT[DHD][64];   // [d][c], reused as sP[r][c]
    __shared__ float sV[64][DHD];    // [c][d]
    const int qt = blockIdx.x;        // query tile 0..31
    const int bh = blockIdx.y;        // 0..31
    const int b = bh >> 4, h = bh & 15;
    const int tid = threadIdx.x;
    const int tx = tid & 15, ty = tid >> 4;
    const int lr = tid >> 2;          // 0..63
    const int lc = (tid & 3) << 4;    // 0,16,32,48

    // load Q tile (transposed into smem)
    {
        const float* src = g_qkv + ((size_t)(b * LSEQ + qt * 64 + lr) * 3 + 0) * CDIM + h * DHD + lc;
        float tmp[16];
        *(float4*)(tmp + 0)  = ((const float4*)src)[0];
        *(float4*)(tmp + 4)  = ((const float4*)src)[1];
        *(float4*)(tmp + 8)  = ((const float4*)src)[2];
        *(float4*)(tmp + 12) = ((const float4*)src)[3];
        #pragma unroll
        for (int u = 0; u < 16; u++) sQT[lc + u][lr] = tmp[u];
    }

    float m_prev[4], l_sum[4], o[4][4];
    #pragma unroll
    for (int i = 0; i < 4; i++) {
        m_prev[i] = -1e30f; l_sum[i] = 0.f;
        #pragma unroll
        for (int j = 0; j < 4; j++) o[i][j] = 0.f;
    }

    for (int kt = 0; kt < LSEQ / 64; kt++) {
        __syncthreads();   // prior P@V (and Q write on iter 0) done before smem reuse
        {
            const float* ks = g_qkv + ((size_t)(b * LSEQ + kt * 64 + lr) * 3 + 1) * CDIM + h * DHD + lc;
            const float* vs = g_qkv + ((size_t)(b * LSEQ + kt * 64 + lr) * 3 + 2) * CDIM + h * DHD + lc;
            float tmp[16];
            *(float4*)(tmp + 0)  = ((const float4*)ks)[0];
            *(float4*)(tmp + 4)  = ((const float4*)ks)[1];
            *(float4*)(tmp + 8)  = ((const float4*)ks)[2];
            *(float4*)(tmp + 12) = ((const float4*)ks)[3];
            #pragma unroll
            for (int u = 0; u < 16; u++) sKT[lc + u][lr] = tmp[u];
            ((float4*)&sV[lr][lc])[0] = ((const float4*)vs)[0];
            ((float4*)&sV[lr][lc])[1] = ((const float4*)vs)[1];
            ((float4*)&sV[lr][lc])[2] = ((const float4*)vs)[2];
            ((float4*)&sV[lr][lc])[3] = ((const float4*)vs)[3];
        }
        __syncthreads();

        float s[4][4] = {};
        #pragma unroll 8
        for (int d = 0; d < DHD; d++) {
            float4 a  = *(const float4*)&sQT[d][ty * 4];
            float4 bb = *(const float4*)&sKT[d][tx * 4];
            s[0][0] += a.x * bb.x; s[0][1] += a.x * bb.y; s[0][2] += a.x * bb.z; s[0][3] += a.x * bb.w;
            s[1][0] += a.y * bb.x; s[1][1] += a.y * bb.y; s[1][2] += a.y * bb.z; s[1][3] += a.y * bb.w;
            s[2][0] += a.z * bb.x; s[2][1] += a.z * bb.y; s[2][2] += a.z * bb.z; s[2][3] += a.z * bb.w;
            s[3][0] += a.w * bb.x; s[3][1] += a.w * bb.y; s[3][2] += a.w * bb.z; s[3][3] += a.w * bb.w;
        }
        // + attn_bias
        #pragma unroll
        for (int i = 0; i < 4; i++) {
            float4 bv = *(const float4*)(abias + (size_t)(qt * 64 + ty * 4 + i) * LSEQ + kt * 64 + tx * 4);
            s[i][0] += bv.x; s[i][1] += bv.y; s[i][2] += bv.z; s[i][3] += bv.w;
        }
        // online softmax
        #pragma unroll
        for (int i = 0; i < 4; i++) {
            float mx = fmaxf(fmaxf(s[i][0], s[i][1]), fmaxf(s[i][2], s[i][3]));
            #pragma unroll
            for (int msk = 8; msk; msk >>= 1) mx = fmaxf(mx, __shfl_xor_sync(0xffffffffu, mx, msk));
            float mn = fmaxf(m_prev[i], mx);
            float al = __expf(m_prev[i] - mn);
            float rs = 0.f;
            #pragma unroll
            for (int j = 0; j < 4; j++) { s[i][j] = __expf(s[i][j] - mn); rs += s[i][j]; }
            #pragma unroll
            for (int msk = 8; msk; msk >>= 1) rs += __shfl_xor_sync(0xffffffffu, rs, msk);
            l_sum[i] = l_sum[i] * al + rs;
            m_prev[i] = mn;
            #pragma unroll
            for (int j = 0; j < 4; j++) o[i][j] *= al;
        }
        __syncthreads();   // all reads of sKT done
        // write P -> sP (reuse sKT) as [r][c]
        #pragma unroll
        for (int i = 0; i < 4; i++)
            *(float4*)&sKT[ty * 4 + i][tx * 4] = make_float4(s[i][0], s[i][1], s[i][2], s[i][3]);
        __syncthreads();
        // o += P @ V
        #pragma unroll 4
        for (int kk = 0; kk < 64; kk++) {
            float4 vv = *(const float4*)&sV[kk][tx * 4];
            float p0 = sKT[ty * 4 + 0][kk];
            float p1 = sKT[ty * 4 + 1][kk];
            float p2 = sKT[ty * 4 + 2][kk];
            float p3 = sKT[ty * 4 + 3][kk];
            o[0][0] += p0 * vv.x; o[0][1] += p0 * vv.y; o[0][2] += p0 * vv.z; o[0][3] += p0 * vv.w;
            o[1][0] += p1 * vv.x; o[1][1] += p1 * vv.y; o[1][2] += p1 * vv.z; o[1][3] += p1 * vv.w;
            o[2][0] += p2 * vv.x; o[2][1] += p2 * vv.y; o[2][2] += p2 * vv.z; o[2][3] += p2 * vv.w;
            o[3][0] += p3 * vv.x; o[3][1] += p3 * vv.y; o[3][2] += p3 * vv.z; o[3][3] += p3 * vv.w;
        }
    }
    // write out to [B*L, C] layout (head-interleaved)
    #pragma unroll
    for (int i = 0; i < 4; i++) {
        float inv = 1.f / l_sum[i];
        size_t off = ((size_t)(b * LSEQ + qt * 64 + ty * 4 + i)) * CDIM + h * DHD + tx * 4;
        *(float4*)(out + off) = make_float4(o[i][0] * inv, o[i][1] * inv, o[i][2] * inv, o[i][3] * inv);
    }
}

// ---------------- launch ----------------
extern "C" void kernel_launch(void* const* d_in, const int* in_sizes, int n_in,
                              void* d_out, int out_size)
{
    const float* x         = (const float*)d_in[0];
    const float* cond_BD   = (const float*)d_in[1];
    const float* attn_bias = (const float*)d_in[2];
    const float* qkv_w     = (const float*)d_in[3];
    const float* q_bias    = (const float*)d_in[4];
    const float* v_bias    = (const float*)d_in[5];
    const float* scale_mul = (const float*)d_in[6];
    const float* proj_w    = (const float*)d_in[7];
    const float* proj_b    = (const float*)d_in[8];
    const float* fc1_w     = (const float*)d_in[9];
    const float* fc1_b     = (const float*)d_in[10];
    const float* fc2_w     = (const float*)d_in[11];
    const float* fc2_b     = (const float*)d_in[12];
    const float* ada_w     = (const float*)d_in[13];
    const float* ada_b     = (const float*)d_in[14];
    float* outp = (float*)d_out;

    float *p_h, *p_qkv, *p_attn, *p_x1, *p_ff;
    cudaGetSymbolAddress((void**)&p_h, g_h);
    cudaGetSymbolAddress((void**)&p_qkv, g_qkv);
    cudaGetSymbolAddress((void**)&p_attn, g_attn);
    cudaGetSymbolAddress((void**)&p_x1, g_x1);
    cudaGetSymbolAddress((void**)&p_ff, g_ff);

    // 1) adaLN coefficients
    ada_kernel<<<dim3(6 * CDIM / 4, BATCH), 128>>>(cond_BD, ada_w, ada_b);
    // 2) h = LN(x)*(s1+1)+sh1   (chunks: g1=0,g2=1,s1=2,s2=3,sh1=4,sh2=5)
    ln_mod_kernel<<<NROWS, 256>>>(x, p_h, 2, 4);
    // 3) qkv = h @ qkv_w^T  (biases applied in qkv_norm)
    sgemm_kernel<<<dim3(3 * CDIM / 128, NROWS / 128), 256>>>(
        NROWS, 3 * CDIM, CDIM, p_h, qkv_w, nullptr, p_qkv, nullptr, -1, 0);
    // 4) bias + per-head L2 norm + scale
    qkv_norm_kernel<<<NROWS * 3 * HEADS / 8, 256>>>(q_bias, v_bias, scale_mul);
    // 5) attention
    flash_kernel<<<dim3(LSEQ / 64, BATCH * HEADS), 256>>>(attn_bias, p_attn);
    // 6) x1 = x + (attn @ proj_w^T + proj_b) * g1
    sgemm_kernel<<<dim3(CDIM / 128, NROWS / 128), 256>>>(
        NROWS, CDIM, CDIM, p_attn, proj_w, proj_b, p_x1, x, 0, 0);
    // 7) h = LN(x1)*(s2+1)+sh2
    ln_mod_kernel<<<NROWS, 256>>>(p_x1, p_h, 3, 5);
    // 8) ff = gelu(h @ fc1_w^T + fc1_b)
    sgemm_kernel<<<dim3(DFF / 128, NROWS / 128), 256>>>(
        NROWS, DFF, CDIM, p_h, fc1_w, fc1_b, p_ff, nullptr, -1, 1);
    // 9) out = x1 + (ff @ fc2_w^T + fc2_b) * g2
    sgemm_kernel<<<dim3(CDIM / 128, NROWS / 128), 256>>>(
        NROWS, CDIM, DFF, p_ff, fc2_w, fc2_b, outp, p_x1, 1, 0);
}

// round 4
// speedup vs baseline: 1.9746x; 1.9746x over previous
#include <cuda_runtime.h>
#include <cstdint>
#include <cstddef>

#define CDIM 1024
#define HEADS 16
#define DHD 64
#define LSEQ 2048
#define BATCH 2
#define DFF 4096
#define NROWS (BATCH*LSEQ)   /* 4096 */

// ---------------- scratch (device globals: alloc-free) ----------------
__device__ float g_ada[BATCH * 6 * CDIM];                 // [B,6,C]
__device__ float g_h[(size_t)NROWS * CDIM];               // LN-mod output
__device__ float g_qkv[(size_t)NROWS * 3 * CDIM];         // [B*L, 3, H, DH]
__device__ float g_attn[(size_t)NROWS * CDIM];            // attention out [B*L, C]
__device__ float g_x1[(size_t)NROWS * CDIM];              // x after attn residual
__device__ float g_ff[(size_t)NROWS * DFF];               // fc1 output

// ================= helpers =================
__device__ __forceinline__ uint32_t smem_u32(const void* p) {
    uint32_t a;
    asm("{ .reg .u64 t; cvta.to.shared.u64 t, %1; cvt.u32.u64 %0, t; }" : "=r"(a) : "l"(p));
    return a;
}
__device__ __forceinline__ void cpasync16(uint32_t dst, const void* src) {
    asm volatile("cp.async.cg.shared.global [%0], [%1], 16;" :: "r"(dst), "l"(src));
}
__device__ __forceinline__ void cp_commit() { asm volatile("cp.async.commit_group;" ::: "memory"); }
__device__ __forceinline__ void cp_wait2()  { asm volatile("cp.async.wait_group 2;" ::: "memory"); }

__device__ __forceinline__ uint32_t f2tf(float f) {
    uint32_t r;
    asm("cvt.rna.tf32.f32 %0, %1;" : "=r"(r) : "f"(f));
    return r;
}
__device__ __forceinline__ void mma_tf32(float* c,
    uint32_t a0, uint32_t a1, uint32_t a2, uint32_t a3, uint32_t b0, uint32_t b1)
{
    asm volatile(
        "mma.sync.aligned.m16n8k8.row.col.f32.tf32.tf32.f32 "
        "{%0,%1,%2,%3},{%4,%5,%6,%7},{%8,%9},{%0,%1,%2,%3};"
        : "+f"(c[0]), "+f"(c[1]), "+f"(c[2]), "+f"(c[3])
        : "r"(a0), "r"(a1), "r"(a2), "r"(a3), "r"(b0), "r"(b1));
}

// ---------------- ada = silu(cond) @ ada_w.T + ada_b ----------------
__global__ __launch_bounds__(128) void ada_kernel(
    const float* __restrict__ cond, const float* __restrict__ ada_w,
    const float* __restrict__ ada_b)
{
    const int warp = threadIdx.x >> 5;
    const int lane = threadIdx.x & 31;
    const int o = blockIdx.x * 4 + warp;
    const int b = blockIdx.y;
    const float* wr = ada_w + (size_t)o * CDIM;
    const float* cr = cond + b * CDIM;
    float s = 0.f;
    for (int k = lane; k < CDIM; k += 32) {
        float c = cr[k];
        float si = c / (1.f + expf(-c));
        s += si * wr[k];
    }
    #pragma unroll
    for (int m = 16; m; m >>= 1) s += __shfl_xor_sync(0xffffffffu, s, m);
    if (lane == 0) g_ada[b * 6 * CDIM + o] = s + ada_b[o];
}

// ---------------- h = LN(x) * (scale+1) + shift ----------------
__global__ __launch_bounds__(256) void ln_mod_kernel(
    const float* __restrict__ x, float* __restrict__ h, int sc, int sh)
{
    __shared__ float red[2];
    const int row = blockIdx.x;
    const int b = row >> 11;
    const float* xr = x + (size_t)row * CDIM;
    float v[4];
    float s = 0.f, ss = 0.f;
    #pragma unroll
    for (int u = 0; u < 4; u++) {
        v[u] = xr[threadIdx.x + u * 256];
        s += v[u]; ss += v[u] * v[u];
    }
    #pragma unroll
    for (int m = 16; m; m >>= 1) {
        s  += __shfl_xor_sync(0xffffffffu, s, m);
        ss += __shfl_xor_sync(0xffffffffu, ss, m);
    }
    __shared__ float ws[16];
    int w = threadIdx.x >> 5, ln = threadIdx.x & 31;
    if (ln == 0) { ws[w] = s; ws[8 + w] = ss; }
    __syncthreads();
    if (threadIdx.x == 0) {
        float S = 0.f, SS = 0.f;
        #pragma unroll
        for (int i = 0; i < 8; i++) { S += ws[i]; SS += ws[8 + i]; }
        float m = S * (1.f / CDIM);
        float var = SS * (1.f / CDIM) - m * m;
        red[0] = m;
        red[1] = rsqrtf(var + 1e-6f);
    }
    __syncthreads();
    const float mean = red[0], rstd = red[1];
    const float* ap = g_ada + b * 6 * CDIM;
    #pragma unroll
    for (int u = 0; u < 4; u++) {
        int c = threadIdx.x + u * 256;
        h[(size_t)row * CDIM + c] =
            (v[u] - mean) * rstd * (ap[sc * CDIM + c] + 1.f) + ap[sh * CDIM + c];
    }
}

// ================= tf32 mma.sync GEMM: C[M,N] = A[M,K] @ W[N,K]^T =================
// 128x128 CTA tile, BK=32, 4-stage cp.async pipeline, 8 warps (2x4), 64x32/warp.
#define TC_STAGES 4
#define TC_STR 36                       /* floats per 32-elem row (+4 pad) */
#define TC_MAT_FLOATS (128 * TC_STR)    /* 4608 */
#define TC_STAGE_BYTES (2 * TC_MAT_FLOATS * 4)  /* 36864: A then B */
#define TC_SMEM (TC_STAGES * TC_STAGE_BYTES)    /* 147456 */

__global__ __launch_bounds__(256, 1)
void tc_gemm(int K, int N,
             const float* __restrict__ A, const float* __restrict__ W,
             const float* __restrict__ bias, float* __restrict__ C,
             const float* __restrict__ res, int gate_chunk, int act)
{
    extern __shared__ float smf[];
    const uint32_t sb = smem_u32(smf);
    const int tid = threadIdx.x;
    const int wid = tid >> 5, lane = tid & 31;
    const int wm = wid & 1, wn = wid >> 1;       // 2 x 4 warp grid
    const int gid = lane >> 2, tig = lane & 3;
    const int m0 = blockIdx.y * 128, n0 = blockIdx.x * 128;
    const int NC = K >> 5;

    // cooperative cp.async of one BK=32 chunk (A[128x32] + W[128x32])
    auto load_chunk = [&](int c) {
        const uint32_t base = sb + (c & (TC_STAGES - 1)) * TC_STAGE_BYTES;
        const int k0 = c << 5;
        #pragma unroll
        for (int t = 0; t < 4; t++) {
            int slot = tid + t * 256;        // 0..1023
            int row = slot >> 3;             // 0..127
            int q = slot & 7;                // float4 index in 32-float row
            uint32_t off = (uint32_t)(row * TC_STR + q * 4) * 4u;
            cpasync16(base + off, A + (size_t)(m0 + row) * K + k0 + q * 4);
            cpasync16(base + TC_MAT_FLOATS * 4 + off, W + (size_t)(n0 + row) * K + k0 + q * 4);
        }
    };

    #pragma unroll
    for (int c = 0; c < TC_STAGES - 1; c++) { load_chunk(c); cp_commit(); }

    float acc[4][4][4];
    #pragma unroll
    for (int i = 0; i < 4; i++)
        #pragma unroll
        for (int j = 0; j < 4; j++)
            #pragma unroll
            for (int u = 0; u < 4; u++) acc[i][j][u] = 0.f;

    for (int c = 0; c < NC; c++) {
        cp_wait2();          // wait_group(TC_STAGES-2): chunk c resident
        __syncthreads();
        const float* sA = smf + (size_t)(c & (TC_STAGES - 1)) * (TC_STAGE_BYTES / 4);
        const float* sB = sA + TC_MAT_FLOATS;
        #pragma unroll
        for (int ks = 0; ks < 4; ks++) {
            const int k = ks * 8 + tig;
            uint32_t a[4][4];
            #pragma unroll
            for (int mt = 0; mt < 4; mt++) {
                const int r = wm * 64 + mt * 16 + gid;
                a[mt][0] = f2tf(sA[r * TC_STR + k]);
                a[mt][1] = f2tf(sA[(r + 8) * TC_STR + k]);
                a[mt][2] = f2tf(sA[r * TC_STR + k + 4]);
                a[mt][3] = f2tf(sA[(r + 8) * TC_STR + k + 4]);
            }
            uint32_t b[4][2];
            #pragma unroll
            for (int nt = 0; nt < 4; nt++) {
                const int r = wn * 32 + nt * 8 + gid;
                b[nt][0] = f2tf(sB[r * TC_STR + k]);
                b[nt][1] = f2tf(sB[r * TC_STR + k + 4]);
            }
            #pragma unroll
            for (int mt = 0; mt < 4; mt++)
                #pragma unroll
                for (int nt = 0; nt < 4; nt++)
                    mma_tf32(acc[mt][nt], a[mt][0], a[mt][1], a[mt][2], a[mt][3],
                             b[nt][0], b[nt][1]);
        }
        __syncthreads();     // all warps done reading before overwriting this stage
        if (c + TC_STAGES - 1 < NC) load_chunk(c + TC_STAGES - 1);
        cp_commit();         // commit every iter (possibly empty) to keep group counts valid
    }

    // ---- fused epilogue, direct float2 stores ----
    #pragma unroll
    for (int mt = 0; mt < 4; mt++) {
        #pragma unroll
        for (int half = 0; half < 2; half++) {
            const int m = m0 + wm * 64 + mt * 16 + gid + half * 8;
            const int bb = m >> 11;
            const float* ap = g_ada + bb * 6 * CDIM;
            #pragma unroll
            for (int nt = 0; nt < 4; nt++) {
                const int n = n0 + wn * 32 + nt * 8 + tig * 2;
                float v0 = acc[mt][nt][half * 2];
                float v1 = acc[mt][nt][half * 2 + 1];
                if (bias) { v0 += bias[n]; v1 += bias[n + 1]; }
                if (act == 1) {
                    float t3 = v0 * v0 * v0;
                    v0 = 0.5f * v0 * (1.f + tanhf(0.7978845608028654f * (v0 + 0.044715f * t3)));
                    t3 = v1 * v1 * v1;
                    v1 = 0.5f * v1 * (1.f + tanhf(0.7978845608028654f * (v1 + 0.044715f * t3)));
                }
                if (gate_chunk >= 0) {
                    v0 *= ap[gate_chunk * CDIM + n];
                    v1 *= ap[gate_chunk * CDIM + n + 1];
                }
                if (res) {
                    v0 += res[(size_t)m * N + n];
                    v1 += res[(size_t)m * N + n + 1];
                }
                *(float2*)(C + (size_t)m * N + n) = make_float2(v0, v1);
            }
        }
    }
}

// ---------------- qkv: add biases, L2-normalize q/k, q *= exp(min(scale_mul,log100)) ----------------
__global__ __launch_bounds__(256) void qkv_norm_kernel(
    const float* __restrict__ q_bias, const float* __restrict__ v_bias,
    const float* __restrict__ scale_mul)
{
    const int gw = blockIdx.x * 8 + (threadIdx.x >> 5);
    const int lane = threadIdx.x & 31;
    const int h = gw & 15;
    const int t = (gw >> 4) % 3;
    const int bl = gw / 48;
    float* p = g_qkv + ((size_t)bl * 3 + t) * CDIM + h * DHD;
    float v0 = p[lane], v1 = p[lane + 32];
    if (t == 0) { v0 += q_bias[h * DHD + lane]; v1 += q_bias[h * DHD + lane + 32]; }
    else if (t == 2) { v0 += v_bias[h * DHD + lane]; v1 += v_bias[h * DHD + lane + 32]; }
    if (t < 2) {
        float ss = v0 * v0 + v1 * v1;
        #pragma unroll
        for (int m = 16; m; m >>= 1) ss += __shfl_xor_sync(0xffffffffu, ss, m);
        float r = rsqrtf(fmaxf(ss, 1e-24f));
        if (t == 0) r *= expf(fminf(scale_mul[h], 4.605170185988092f));
        v0 *= r; v1 *= r;
    }
    p[lane] = v0; p[lane + 32] = v1;
}

// ---------------- flash attention: per (b,h), 64-query tiles, online softmax ----------------
__global__ __launch_bounds__(256) void flash_kernel(
    const float* __restrict__ abias, float* __restrict__ out)
{
    __shared__ float sQT[DHD][64];
    __shared__ float sKT[DHD][64];
    __shared__ float sV[64][DHD];
    const int qt = blockIdx.x;
    const int bh = blockIdx.y;
    const int b = bh >> 4, h = bh & 15;
    const int tid = threadIdx.x;
    const int tx = tid & 15, ty = tid >> 4;
    const int lr = tid >> 2;
    const int lc = (tid & 3) << 4;

    {
        const float* src = g_qkv + ((size_t)(b * LSEQ + qt * 64 + lr) * 3 + 0) * CDIM + h * DHD + lc;
        float tmp[16];
        *(float4*)(tmp + 0)  = ((const float4*)src)[0];
        *(float4*)(tmp + 4)  = ((const float4*)src)[1];
        *(float4*)(tmp + 8)  = ((const float4*)src)[2];
        *(float4*)(tmp + 12) = ((const float4*)src)[3];
        #pragma unroll
        for (int u = 0; u < 16; u++) sQT[lc + u][lr] = tmp[u];
    }

    float m_prev[4], l_sum[4], o[4][4];
    #pragma unroll
    for (int i = 0; i < 4; i++) {
        m_prev[i] = -1e30f; l_sum[i] = 0.f;
        #pragma unroll
        for (int j = 0; j < 4; j++) o[i][j] = 0.f;
    }

    for (int kt = 0; kt < LSEQ / 64; kt++) {
        __syncthreads();
        {
            const float* ks = g_qkv + ((size_t)(b * LSEQ + kt * 64 + lr) * 3 + 1) * CDIM + h * DHD + lc;
            const float* vs = g_qkv + ((size_t)(b * LSEQ + kt * 64 + lr) * 3 + 2) * CDIM + h * DHD + lc;
            float tmp[16];
            *(float4*)(tmp + 0)  = ((const float4*)ks)[0];
            *(float4*)(tmp + 4)  = ((const float4*)ks)[1];
            *(float4*)(tmp + 8)  = ((const float4*)ks)[2];
            *(float4*)(tmp + 12) = ((const float4*)ks)[3];
            #pragma unroll
            for (int u = 0; u < 16; u++) sKT[lc + u][lr] = tmp[u];
            ((float4*)&sV[lr][lc])[0] = ((const float4*)vs)[0];
            ((float4*)&sV[lr][lc])[1] = ((const float4*)vs)[1];
            ((float4*)&sV[lr][lc])[2] = ((const float4*)vs)[2];
            ((float4*)&sV[lr][lc])[3] = ((const float4*)vs)[3];
        }
        __syncthreads();

        float s[4][4] = {};
        #pragma unroll 8
        for (int d = 0; d < DHD; d++) {
            float4 a  = *(const float4*)&sQT[d][ty * 4];
            float4 bb = *(const float4*)&sKT[d][tx * 4];
            s[0][0] += a.x * bb.x; s[0][1] += a.x * bb.y; s[0][2] += a.x * bb.z; s[0][3] += a.x * bb.w;
            s[1][0] += a.y * bb.x; s[1][1] += a.y * bb.y; s[1][2] += a.y * bb.z; s[1][3] += a.y * bb.w;
            s[2][0] += a.z * bb.x; s[2][1] += a.z * bb.y; s[2][2] += a.z * bb.z; s[2][3] += a.z * bb.w;
            s[3][0] += a.w * bb.x; s[3][1] += a.w * bb.y; s[3][2] += a.w * bb.z; s[3][3] += a.w * bb.w;
        }
        #pragma unroll
        for (int i = 0; i < 4; i++) {
            float4 bv = *(const float4*)(abias + (size_t)(qt * 64 + ty * 4 + i) * LSEQ + kt * 64 + tx * 4);
            s[i][0] += bv.x; s[i][1] += bv.y; s[i][2] += bv.z; s[i][3] += bv.w;
        }
        #pragma unroll
        for (int i = 0; i < 4; i++) {
            float mx = fmaxf(fmaxf(s[i][0], s[i][1]), fmaxf(s[i][2], s[i][3]));
            #pragma unroll
            for (int msk = 8; msk; msk >>= 1) mx = fmaxf(mx, __shfl_xor_sync(0xffffffffu, mx, msk));
            float mn = fmaxf(m_prev[i], mx);
            float al = __expf(m_prev[i] - mn);
            float rs = 0.f;
            #pragma unroll
            for (int j = 0; j < 4; j++) { s[i][j] = __expf(s[i][j] - mn); rs += s[i][j]; }
            #pragma unroll
            for (int msk = 8; msk; msk >>= 1) rs += __shfl_xor_sync(0xffffffffu, rs, msk);
            l_sum[i] = l_sum[i] * al + rs;
            m_prev[i] = mn;
            #pragma unroll
            for (int j = 0; j < 4; j++) o[i][j] *= al;
        }
        __syncthreads();
        #pragma unroll
        for (int i = 0; i < 4; i++)
            *(float4*)&sKT[ty * 4 + i][tx * 4] = make_float4(s[i][0], s[i][1], s[i][2], s[i][3]);
        __syncthreads();
        #pragma unroll 4
        for (int kk = 0; kk < 64; kk++) {
            float4 vv = *(const float4*)&sV[kk][tx * 4];
            float p0 = sKT[ty * 4 + 0][kk];
            float p1 = sKT[ty * 4 + 1][kk];
            float p2 = sKT[ty * 4 + 2][kk];
            float p3 = sKT[ty * 4 + 3][kk];
            o[0][0] += p0 * vv.x; o[0][1] += p0 * vv.y; o[0][2] += p0 * vv.z; o[0][3] += p0 * vv.w;
            o[1][0] += p1 * vv.x; o[1][1] += p1 * vv.y; o[1][2] += p1 * vv.z; o[1][3] += p1 * vv.w;
            o[2][0] += p2 * vv.x; o[2][1] += p2 * vv.y; o[2][2] += p2 * vv.z; o[2][3] += p2 * vv.w;
            o[3][0] += p3 * vv.x; o[3][1] += p3 * vv.y; o[3][2] += p3 * vv.z; o[3][3] += p3 * vv.w;
        }
    }
    #pragma unroll
    for (int i = 0; i < 4; i++) {
        float inv = 1.f / l_sum[i];
        size_t off = ((size_t)(b * LSEQ + qt * 64 + ty * 4 + i)) * CDIM + h * DHD + tx * 4;
        *(float4*)(out + off) = make_float4(o[i][0] * inv, o[i][1] * inv, o[i][2] * inv, o[i][3] * inv);
    }
}

// ---------------- launch ----------------
extern "C" void kernel_launch(void* const* d_in, const int* in_sizes, int n_in,
                              void* d_out, int out_size)
{
    const float* x         = (const float*)d_in[0];
    const float* cond_BD   = (const float*)d_in[1];
    const float* attn_bias = (const float*)d_in[2];
    const float* qkv_w     = (const float*)d_in[3];
    const float* q_bias    = (const float*)d_in[4];
    const float* v_bias    = (const float*)d_in[5];
    const float* scale_mul = (const float*)d_in[6];
    const float* proj_w    = (const float*)d_in[7];
    const float* proj_b    = (const float*)d_in[8];
    const float* fc1_w     = (const float*)d_in[9];
    const float* fc1_b     = (const float*)d_in[10];
    const float* fc2_w     = (const float*)d_in[11];
    const float* fc2_b     = (const float*)d_in[12];
    const float* ada_w     = (const float*)d_in[13];
    const float* ada_b     = (const float*)d_in[14];
    float* outp = (float*)d_out;

    float *p_h, *p_qkv, *p_attn, *p_x1, *p_ff;
    cudaGetSymbolAddress((void**)&p_h, g_h);
    cudaGetSymbolAddress((void**)&p_qkv, g_qkv);
    cudaGetSymbolAddress((void**)&p_attn, g_attn);
    cudaGetSymbolAddress((void**)&p_x1, g_x1);
    cudaGetSymbolAddress((void**)&p_ff, g_ff);

    cudaFuncSetAttribute(tc_gemm, cudaFuncAttributeMaxDynamicSharedMemorySize, TC_SMEM);

    // 1) adaLN coefficients
    ada_kernel<<<dim3(6 * CDIM / 4, BATCH), 128>>>(cond_BD, ada_w, ada_b);
    // 2) h = LN(x)*(s1+1)+sh1   (chunks: g1=0,g2=1,s1=2,s2=3,sh1=4,sh2=5)
    ln_mod_kernel<<<NROWS, 256>>>(x, p_h, 2, 4);
    // 3) qkv = h @ qkv_w^T
    tc_gemm<<<dim3(3 * CDIM / 128, NROWS / 128), 256, TC_SMEM>>>(
        CDIM, 3 * CDIM, p_h, qkv_w, nullptr, p_qkv, nullptr, -1, 0);
    // 4) bias + per-head L2 norm + scale
    qkv_norm_kernel<<<NROWS * 3 * HEADS / 8, 256>>>(q_bias, v_bias, scale_mul);
    // 5) attention
    flash_kernel<<<dim3(LSEQ / 64, BATCH * HEADS), 256>>>(attn_bias, p_attn);
    // 6) x1 = x + (attn @ proj_w^T + proj_b) * g1
    tc_gemm<<<dim3(CDIM / 128, NROWS / 128), 256, TC_SMEM>>>(
        CDIM, CDIM, p_attn, proj_w, proj_b, p_x1, x, 0, 0);
    // 7) h = LN(x1)*(s2+1)+sh2
    ln_mod_kernel<<<NROWS, 256>>>(p_x1, p_h, 3, 5);
    // 8) ff = gelu(h @ fc1_w^T + fc1_b)
    tc_gemm<<<dim3(DFF / 128, NROWS / 128), 256, TC_SMEM>>>(
        CDIM, DFF, p_h, fc1_w, fc1_b, p_ff, nullptr, -1, 1);
    // 9) out = x1 + (ff @ fc2_w^T + fc2_b) * g2
    tc_gemm<<<dim3(CDIM / 128, NROWS / 128), 256, TC_SMEM>>>(
        DFF, CDIM, p_ff, fc2_w, fc2_b, outp, p_x1, 1, 0);
}

// round 5
// speedup vs baseline: 2.4796x; 1.2558x over previous
#include <cuda_runtime.h>
#include <cstdint>
#include <cstddef>

#define CDIM 1024
#define HEADS 16
#define DHD 64
#define LSEQ 2048
#define BATCH 2
#define DFF 4096
#define NROWS (BATCH*LSEQ)   /* 4096 */

// ---------------- scratch (device globals: alloc-free) ----------------
__device__ float g_ada[BATCH * 6 * CDIM];                 // [B,6,C]
__device__ float g_h[(size_t)NROWS * CDIM];               // LN-mod output
__device__ float g_qkv[(size_t)NROWS * 3 * CDIM];         // [B*L, 3, H, DH]
__device__ float g_attn[(size_t)NROWS * CDIM];            // attention out [B*L, C]
__device__ float g_x1[(size_t)NROWS * CDIM];              // x after attn residual
__device__ float g_ff[(size_t)NROWS * DFF];               // fc1 output

// ================= helpers =================
__device__ __forceinline__ uint32_t smem_u32(const void* p) {
    uint32_t a;
    asm("{ .reg .u64 t; cvta.to.shared.u64 t, %1; cvt.u32.u64 %0, t; }" : "=r"(a) : "l"(p));
    return a;
}
__device__ __forceinline__ void cpasync16(uint32_t dst, const void* src) {
    asm volatile("cp.async.cg.shared.global [%0], [%1], 16;" :: "r"(dst), "l"(src));
}
__device__ __forceinline__ void cp_commit() { asm volatile("cp.async.commit_group;" ::: "memory"); }
__device__ __forceinline__ void cp_wait2()  { asm volatile("cp.async.wait_group 2;" ::: "memory"); }

__device__ __forceinline__ uint32_t f2tf(float f) {
    uint32_t r;
    asm("cvt.rna.tf32.f32 %0, %1;" : "=r"(r) : "f"(f));
    return r;
}
__device__ __forceinline__ void mma_tf32(float* c,
    uint32_t a0, uint32_t a1, uint32_t a2, uint32_t a3, uint32_t b0, uint32_t b1)
{
    asm volatile(
        "mma.sync.aligned.m16n8k8.row.col.f32.tf32.tf32.f32 "
        "{%0,%1,%2,%3},{%4,%5,%6,%7},{%8,%9},{%0,%1,%2,%3};"
        : "+f"(c[0]), "+f"(c[1]), "+f"(c[2]), "+f"(c[3])
        : "r"(a0), "r"(a1), "r"(a2), "r"(a3), "r"(b0), "r"(b1));
}

// FMA-pipe exp (no MUFU): magic-number rounding + degree-5 poly, |rel err| ~2e-6
__device__ __forceinline__ float fexp(float x) {
    float t = fmaxf(x, -87.f) * 1.4426950408889634f;   // log2(e)
    float z = __fadd_rn(t, 12582912.0f);               // round-to-nearest int
    float n = __fsub_rn(z, 12582912.0f);
    int ni = (__float_as_int(z) & 0x7FFFFF) - 0x400000;
    float c = (t - n) * 0.6931471805599453f;           // in [-0.347, 0.347]
    float p = 8.3333333e-3f;
    p = fmaf(p, c, 4.1666667e-2f);
    p = fmaf(p, c, 0.16666667f);
    p = fmaf(p, c, 0.5f);
    p = fmaf(p, c, 1.0f);
    p = fmaf(p, c, 1.0f);
    return p * __int_as_float((ni + 127) << 23);
}

// ---------------- ada = silu(cond) @ ada_w.T + ada_b ----------------
__global__ __launch_bounds__(128) void ada_kernel(
    const float* __restrict__ cond, const float* __restrict__ ada_w,
    const float* __restrict__ ada_b)
{
    const int warp = threadIdx.x >> 5;
    const int lane = threadIdx.x & 31;
    const int o = blockIdx.x * 4 + warp;
    const int b = blockIdx.y;
    const float* wr = ada_w + (size_t)o * CDIM;
    const float* cr = cond + b * CDIM;
    float s = 0.f;
    for (int k = lane; k < CDIM; k += 32) {
        float c = cr[k];
        float si = c / (1.f + expf(-c));
        s += si * wr[k];
    }
    #pragma unroll
    for (int m = 16; m; m >>= 1) s += __shfl_xor_sync(0xffffffffu, s, m);
    if (lane == 0) g_ada[b * 6 * CDIM + o] = s + ada_b[o];
}

// ---------------- h = LN(x) * (scale+1) + shift ----------------
__global__ __launch_bounds__(256) void ln_mod_kernel(
    const float* __restrict__ x, float* __restrict__ h, int sc, int sh)
{
    __shared__ float red[2];
    const int row = blockIdx.x;
    const int b = row >> 11;
    const float* xr = x + (size_t)row * CDIM;
    float v[4];
    float s = 0.f, ss = 0.f;
    #pragma unroll
    for (int u = 0; u < 4; u++) {
        v[u] = xr[threadIdx.x + u * 256];
        s += v[u]; ss += v[u] * v[u];
    }
    #pragma unroll
    for (int m = 16; m; m >>= 1) {
        s  += __shfl_xor_sync(0xffffffffu, s, m);
        ss += __shfl_xor_sync(0xffffffffu, ss, m);
    }
    __shared__ float ws[16];
    int w = threadIdx.x >> 5, ln = threadIdx.x & 31;
    if (ln == 0) { ws[w] = s; ws[8 + w] = ss; }
    __syncthreads();
    if (threadIdx.x == 0) {
        float S = 0.f, SS = 0.f;
        #pragma unroll
        for (int i = 0; i < 8; i++) { S += ws[i]; SS += ws[8 + i]; }
        float m = S * (1.f / CDIM);
        float var = SS * (1.f / CDIM) - m * m;
        red[0] = m;
        red[1] = rsqrtf(var + 1e-6f);
    }
    __syncthreads();
    const float mean = red[0], rstd = red[1];
    const float* ap = g_ada + b * 6 * CDIM;
    #pragma unroll
    for (int u = 0; u < 4; u++) {
        int c = threadIdx.x + u * 256;
        h[(size_t)row * CDIM + c] =
            (v[u] - mean) * rstd * (ap[sc * CDIM + c] + 1.f) + ap[sh * CDIM + c];
    }
}

// ================= tf32 mma.sync GEMM: C[M,N] = A[M,K] @ W[N,K]^T =================
#define TC_STAGES 4
#define TC_STR 36
#define TC_MAT_FLOATS (128 * TC_STR)
#define TC_STAGE_BYTES (2 * TC_MAT_FLOATS * 4)
#define TC_SMEM (TC_STAGES * TC_STAGE_BYTES)

__global__ __launch_bounds__(256, 1)
void tc_gemm(int K, int N,
             const float* __restrict__ A, const float* __restrict__ W,
             const float* __restrict__ bias, float* __restrict__ C,
             const float* __restrict__ res, int gate_chunk, int act)
{
    extern __shared__ float smf[];
    const uint32_t sb = smem_u32(smf);
    const int tid = threadIdx.x;
    const int wid = tid >> 5, lane = tid & 31;
    const int wm = wid & 1, wn = wid >> 1;
    const int gid = lane >> 2, tig = lane & 3;
    const int m0 = blockIdx.y * 128, n0 = blockIdx.x * 128;
    const int NC = K >> 5;

    auto load_chunk = [&](int c) {
        const uint32_t base = sb + (c & (TC_STAGES - 1)) * TC_STAGE_BYTES;
        const int k0 = c << 5;
        #pragma unroll
        for (int t = 0; t < 4; t++) {
            int slot = tid + t * 256;
            int row = slot >> 3;
            int q = slot & 7;
            uint32_t off = (uint32_t)(row * TC_STR + q * 4) * 4u;
            cpasync16(base + off, A + (size_t)(m0 + row) * K + k0 + q * 4);
            cpasync16(base + TC_MAT_FLOATS * 4 + off, W + (size_t)(n0 + row) * K + k0 + q * 4);
        }
    };

    #pragma unroll
    for (int c = 0; c < TC_STAGES - 1; c++) { load_chunk(c); cp_commit(); }

    float acc[4][4][4];
    #pragma unroll
    for (int i = 0; i < 4; i++)
        #pragma unroll
        for (int j = 0; j < 4; j++)
            #pragma unroll
            for (int u = 0; u < 4; u++) acc[i][j][u] = 0.f;

    for (int c = 0; c < NC; c++) {
        cp_wait2();
        __syncthreads();
        const float* sA = smf + (size_t)(c & (TC_STAGES - 1)) * (TC_STAGE_BYTES / 4);
        const float* sB = sA + TC_MAT_FLOATS;
        #pragma unroll
        for (int ks = 0; ks < 4; ks++) {
            const int k = ks * 8 + tig;
            uint32_t a[4][4];
            #pragma unroll
            for (int mt = 0; mt < 4; mt++) {
                const int r = wm * 64 + mt * 16 + gid;
                a[mt][0] = f2tf(sA[r * TC_STR + k]);
                a[mt][1] = f2tf(sA[(r + 8) * TC_STR + k]);
                a[mt][2] = f2tf(sA[r * TC_STR + k + 4]);
                a[mt][3] = f2tf(sA[(r + 8) * TC_STR + k + 4]);
            }
            uint32_t b[4][2];
            #pragma unroll
            for (int nt = 0; nt < 4; nt++) {
                const int r = wn * 32 + nt * 8 + gid;
                b[nt][0] = f2tf(sB[r * TC_STR + k]);
                b[nt][1] = f2tf(sB[r * TC_STR + k + 4]);
            }
            #pragma unroll
            for (int mt = 0; mt < 4; mt++)
                #pragma unroll
                for (int nt = 0; nt < 4; nt++)
                    mma_tf32(acc[mt][nt], a[mt][0], a[mt][1], a[mt][2], a[mt][3],
                             b[nt][0], b[nt][1]);
        }
        __syncthreads();
        if (c + TC_STAGES - 1 < NC) load_chunk(c + TC_STAGES - 1);
        cp_commit();
    }

    #pragma unroll
    for (int mt = 0; mt < 4; mt++) {
        #pragma unroll
        for (int half = 0; half < 2; half++) {
            const int m = m0 + wm * 64 + mt * 16 + gid + half * 8;
            const int bb = m >> 11;
            const float* ap = g_ada + bb * 6 * CDIM;
            #pragma unroll
            for (int nt = 0; nt < 4; nt++) {
                const int n = n0 + wn * 32 + nt * 8 + tig * 2;
                float v0 = acc[mt][nt][half * 2];
                float v1 = acc[mt][nt][half * 2 + 1];
                if (bias) { v0 += bias[n]; v1 += bias[n + 1]; }
                if (act == 1) {
                    float t3 = v0 * v0 * v0;
                    v0 = 0.5f * v0 * (1.f + tanhf(0.7978845608028654f * (v0 + 0.044715f * t3)));
                    t3 = v1 * v1 * v1;
                    v1 = 0.5f * v1 * (1.f + tanhf(0.7978845608028654f * (v1 + 0.044715f * t3)));
                }
                if (gate_chunk >= 0) {
                    v0 *= ap[gate_chunk * CDIM + n];
                    v1 *= ap[gate_chunk * CDIM + n + 1];
                }
                if (res) {
                    v0 += res[(size_t)m * N + n];
                    v1 += res[(size_t)m * N + n + 1];
                }
                *(float2*)(C + (size_t)m * N + n) = make_float2(v0, v1);
            }
        }
    }
}

// ---------------- qkv: add biases, L2-normalize q/k, q *= exp(min(scale_mul,log100)) ----------------
__global__ __launch_bounds__(256) void qkv_norm_kernel(
    const float* __restrict__ q_bias, const float* __restrict__ v_bias,
    const float* __restrict__ scale_mul)
{
    const int gw = blockIdx.x * 8 + (threadIdx.x >> 5);
    const int lane = threadIdx.x & 31;
    const int h = gw & 15;
    const int t = (gw >> 4) % 3;
    const int bl = gw / 48;
    float* p = g_qkv + ((size_t)bl * 3 + t) * CDIM + h * DHD;
    float v0 = p[lane], v1 = p[lane + 32];
    if (t == 0) { v0 += q_bias[h * DHD + lane]; v1 += q_bias[h * DHD + lane + 32]; }
    else if (t == 2) { v0 += v_bias[h * DHD + lane]; v1 += v_bias[h * DHD + lane + 32]; }
    if (t < 2) {
        float ss = v0 * v0 + v1 * v1;
        #pragma unroll
        for (int m = 16; m; m >>= 1) ss += __shfl_xor_sync(0xffffffffu, ss, m);
        float r = rsqrtf(fmaxf(ss, 1e-24f));
        if (t == 0) r *= expf(fminf(scale_mul[h], 4.605170185988092f));
        v0 *= r; v1 *= r;
    }
    p[lane] = v0; p[lane + 32] = v1;
}

// ================= flash attention with tf32 mma.sync =================
// Q tile 128 rows, 8 warps x 16 rows; K tiles of 64. FMA-pipe exp (no MUFU).
#define FA_STR 68
#define FA_SQ   (128 * FA_STR)              /* floats */
#define FA_SK   (64 * FA_STR)
#define FA_SMEM ((FA_SQ + 2 * FA_SK + 8 * 16 * FA_STR) * 4)   /* 104448 B */

__global__ __launch_bounds__(256, 1)
void flash_mma(const float* __restrict__ abias, float* __restrict__ out)
{
    extern __shared__ float sm[];
    float* sQ  = sm;                       // [128][68]
    float* sK  = sQ + FA_SQ;               // [64][68]  (n=kcol, k=d) row-major
    float* sVT = sK + FA_SK;               // [64][68]  (n=d, k=kcol) row-major = V^T
    float* sP  = sVT + FA_SK;              // 8 x [16][68] warp-private

    const int qt = blockIdx.x, bh = blockIdx.y;
    const int b = bh >> 4, h = bh & 15;
    const int tid = threadIdx.x, wid = tid >> 5, lane = tid & 31;
    const int gid = lane >> 2, tig = lane & 3;
    float* sPw = sP + wid * 16 * FA_STR;
    const int qrow0 = qt * 128;
    const int wq0 = wid * 16;

    // load Q tile (row-major)
    for (int i = tid; i < 128 * 16; i += 256) {
        int r = i >> 4, c4 = i & 15;
        float4 v = *(const float4*)(g_qkv +
            ((size_t)(b * LSEQ + qrow0 + r) * 3 + 0) * CDIM + h * DHD + c4 * 4);
        *(float4*)(sQ + r * FA_STR + c4 * 4) = v;
    }

    float oacc[8][4];
    #pragma unroll
    for (int i = 0; i < 8; i++)
        #pragma unroll
        for (int j = 0; j < 4; j++) oacc[i][j] = 0.f;
    float m0r = -1e30f, m1r = -1e30f, l0 = 0.f, l1 = 0.f;

    for (int kt = 0; kt < LSEQ / 64; kt++) {
        __syncthreads();
        // K natural, V transposed
        for (int i = tid; i < 64 * 16; i += 256) {
            int r = i >> 4, c4 = i & 15;
            float4 v = *(const float4*)(g_qkv +
                ((size_t)(b * LSEQ + kt * 64 + r) * 3 + 1) * CDIM + h * DHD + c4 * 4);
            *(float4*)(sK + r * FA_STR + c4 * 4) = v;
            float4 w = *(const float4*)(g_qkv +
                ((size_t)(b * LSEQ + kt * 64 + r) * 3 + 2) * CDIM + h * DHD + c4 * 4);
            int c0 = c4 * 4;
            sVT[(c0 + 0) * FA_STR + r] = w.x;
            sVT[(c0 + 1) * FA_STR + r] = w.y;
            sVT[(c0 + 2) * FA_STR + r] = w.z;
            sVT[(c0 + 3) * FA_STR + r] = w.w;
        }
        __syncthreads();

        // S = Q K^T  (16x64 per warp)
        float sacc[8][4];
        #pragma unroll
        for (int i = 0; i < 8; i++)
            #pragma unroll
            for (int j = 0; j < 4; j++) sacc[i][j] = 0.f;
        #pragma unroll
        for (int ks = 0; ks < 8; ks++) {
            const int k = ks * 8 + tig;
            uint32_t a0 = f2tf(sQ[(wq0 + gid) * FA_STR + k]);
            uint32_t a1 = f2tf(sQ[(wq0 + gid + 8) * FA_STR + k]);
            uint32_t a2 = f2tf(sQ[(wq0 + gid) * FA_STR + k + 4]);
            uint32_t a3 = f2tf(sQ[(wq0 + gid + 8) * FA_STR + k + 4]);
            #pragma unroll
            for (int nt = 0; nt < 8; nt++) {
                uint32_t b0 = f2tf(sK[(nt * 8 + gid) * FA_STR + k]);
                uint32_t b1 = f2tf(sK[(nt * 8 + gid) * FA_STR + k + 4]);
                mma_tf32(sacc[nt], a0, a1, a2, a3, b0, b1);
            }
        }
        // + attn_bias
        {
            const float* bp = abias + (size_t)(qrow0 + wq0) * LSEQ + kt * 64;
            #pragma unroll
            for (int nt = 0; nt < 8; nt++) {
                float2 b01 = *(const float2*)(bp + (size_t)gid * LSEQ + nt * 8 + 2 * tig);
                float2 b23 = *(const float2*)(bp + (size_t)(gid + 8) * LSEQ + nt * 8 + 2 * tig);
                sacc[nt][0] += b01.x; sacc[nt][1] += b01.y;
                sacc[nt][2] += b23.x; sacc[nt][3] += b23.y;
            }
        }
        // online softmax (rows gid and gid+8)
        float mx0 = -1e30f, mx1 = -1e30f;
        #pragma unroll
        for (int nt = 0; nt < 8; nt++) {
            mx0 = fmaxf(mx0, fmaxf(sacc[nt][0], sacc[nt][1]));
            mx1 = fmaxf(mx1, fmaxf(sacc[nt][2], sacc[nt][3]));
        }
        mx0 = fmaxf(mx0, __shfl_xor_sync(0xffffffffu, mx0, 1));
        mx0 = fmaxf(mx0, __shfl_xor_sync(0xffffffffu, mx0, 2));
        mx1 = fmaxf(mx1, __shfl_xor_sync(0xffffffffu, mx1, 1));
        mx1 = fmaxf(mx1, __shfl_xor_sync(0xffffffffu, mx1, 2));
        float mn0 = fmaxf(m0r, mx0), mn1 = fmaxf(m1r, mx1);
        float al0 = fexp(m0r - mn0), al1 = fexp(m1r - mn1);
        float rs0 = 0.f, rs1 = 0.f;
        #pragma unroll
        for (int nt = 0; nt < 8; nt++) {
            sacc[nt][0] = fexp(sacc[nt][0] - mn0);
            sacc[nt][1] = fexp(sacc[nt][1] - mn0);
            sacc[nt][2] = fexp(sacc[nt][2] - mn1);
            sacc[nt][3] = fexp(sacc[nt][3] - mn1);
            rs0 += sacc[nt][0] + sacc[nt][1];
            rs1 += sacc[nt][2] + sacc[nt][3];
        }
        rs0 += __shfl_xor_sync(0xffffffffu, rs0, 1);
        rs0 += __shfl_xor_sync(0xffffffffu, rs0, 2);
        rs1 += __shfl_xor_sync(0xffffffffu, rs1, 1);
        rs1 += __shfl_xor_sync(0xffffffffu, rs1, 2);
        l0 = l0 * al0 + rs0; l1 = l1 * al1 + rs1;
        m0r = mn0; m1r = mn1;
        #pragma unroll
        for (int dt = 0; dt < 8; dt++) {
            oacc[dt][0] *= al0; oacc[dt][1] *= al0;
            oacc[dt][2] *= al1; oacc[dt][3] *= al1;
        }
        // P -> warp-private smem (fragment layout mismatch for tf32 k8)
        #pragma unroll
        for (int nt = 0; nt < 8; nt++) {
            *(float2*)(sPw + gid * FA_STR + nt * 8 + 2 * tig) =
                make_float2(sacc[nt][0], sacc[nt][1]);
            *(float2*)(sPw + (gid + 8) * FA_STR + nt * 8 + 2 * tig) =
                make_float2(sacc[nt][2], sacc[nt][3]);
        }
        __syncwarp();
        // O += P V   (A = P [16 x 64kcol], B = V^T)
        #pragma unroll
        for (int kc = 0; kc < 8; kc++) {
            const int k = kc * 8 + tig;
            uint32_t a0 = f2tf(sPw[gid * FA_STR + k]);
            uint32_t a1 = f2tf(sPw[(gid + 8) * FA_STR + k]);
            uint32_t a2 = f2tf(sPw[gid * FA_STR + k + 4]);
            uint32_t a3 = f2tf(sPw[(gid + 8) * FA_STR + k + 4]);
            #pragma unroll
            for (int dt = 0; dt < 8; dt++) {
                uint32_t b0 = f2tf(sVT[(dt * 8 + gid) * FA_STR + k]);
                uint32_t b1 = f2tf(sVT[(dt * 8 + gid) * FA_STR + k + 4]);
                mma_tf32(oacc[dt], a0, a1, a2, a3, b0, b1);
            }
        }
    }
    // write O / l  to [B*L, C]
    {
        float inv0 = 1.f / l0, inv1 = 1.f / l1;
        const size_t r0 = (size_t)(b * LSEQ + qrow0 + wq0 + gid);
        const size_t r1 = r0 + 8;
        #pragma unroll
        for (int dt = 0; dt < 8; dt++) {
            int col = h * DHD + dt * 8 + 2 * tig;
            *(float2*)(out + r0 * CDIM + col) =
                make_float2(oacc[dt][0] * inv0, oacc[dt][1] * inv0);
            *(float2*)(out + r1 * CDIM + col) =
                make_float2(oacc[dt][2] * inv1, oacc[dt][3] * inv1);
        }
    }
}

// ---------------- launch ----------------
extern "C" void kernel_launch(void* const* d_in, const int* in_sizes, int n_in,
                              void* d_out, int out_size)
{
    const float* x         = (const float*)d_in[0];
    const float* cond_BD   = (const float*)d_in[1];
    const float* attn_bias = (const float*)d_in[2];
    const float* qkv_w     = (const float*)d_in[3];
    const float* q_bias    = (const float*)d_in[4];
    const float* v_bias    = (const float*)d_in[5];
    const float* scale_mul = (const float*)d_in[6];
    const float* proj_w    = (const float*)d_in[7];
    const float* proj_b    = (const float*)d_in[8];
    const float* fc1_w     = (const float*)d_in[9];
    const float* fc1_b     = (const float*)d_in[10];
    const float* fc2_w     = (const float*)d_in[11];
    const float* fc2_b     = (const float*)d_in[12];
    const float* ada_w     = (const float*)d_in[13];
    const float* ada_b     = (const float*)d_in[14];
    float* outp = (float*)d_out;

    float *p_h, *p_qkv, *p_attn, *p_x1, *p_ff;
    cudaGetSymbolAddress((void**)&p_h, g_h);
    cudaGetSymbolAddress((void**)&p_qkv, g_qkv);
    cudaGetSymbolAddress((void**)&p_attn, g_attn);
    cudaGetSymbolAddress((void**)&p_x1, g_x1);
    cudaGetSymbolAddress((void**)&p_ff, g_ff);

    cudaFuncSetAttribute(tc_gemm, cudaFuncAttributeMaxDynamicSharedMemorySize, TC_SMEM);
    cudaFuncSetAttribute(flash_mma, cudaFuncAttributeMaxDynamicSharedMemorySize, FA_SMEM);

    // 1) adaLN coefficients
    ada_kernel<<<dim3(6 * CDIM / 4, BATCH), 128>>>(cond_BD, ada_w, ada_b);
    // 2) h = LN(x)*(s1+1)+sh1   (chunks: g1=0,g2=1,s1=2,s2=3,sh1=4,sh2=5)
    ln_mod_kernel<<<NROWS, 256>>>(x, p_h, 2, 4);
    // 3) qkv = h @ qkv_w^T
    tc_gemm<<<dim3(3 * CDIM / 128, NROWS / 128), 256, TC_SMEM>>>(
        CDIM, 3 * CDIM, p_h, qkv_w, nullptr, p_qkv, nullptr, -1, 0);
    // 4) bias + per-head L2 norm + scale
    qkv_norm_kernel<<<NROWS * 3 * HEADS / 8, 256>>>(q_bias, v_bias, scale_mul);
    // 5) attention (tf32 mma)
    flash_mma<<<dim3(LSEQ / 128, BATCH * HEADS), 256, FA_SMEM>>>(attn_bias, p_attn);
    // 6) x1 = x + (attn @ proj_w^T + proj_b) * g1
    tc_gemm<<<dim3(CDIM / 128, NROWS / 128), 256, TC_SMEM>>>(
        CDIM, CDIM, p_attn, proj_w, proj_b, p_x1, x, 0, 0);
    // 7) h = LN(x1)*(s2+1)+sh2
    ln_mod_kernel<<<NROWS, 256>>>(p_x1, p_h, 3, 5);
    // 8) ff = gelu(h @ fc1_w^T + fc1_b)
    tc_gemm<<<dim3(DFF / 128, NROWS / 128), 256, TC_SMEM>>>(
        CDIM, DFF, p_h, fc1_w, fc1_b, p_ff, nullptr, -1, 1);
    // 9) out = x1 + (ff @ fc2_w^T + fc2_b) * g2
    tc_gemm<<<dim3(CDIM / 128, NROWS / 128), 256, TC_SMEM>>>(
        DFF, CDIM, p_ff, fc2_w, fc2_b, outp, p_x1, 1, 0);
}

// round 7
// speedup vs baseline: 3.9597x; 1.5970x over previous
#include <cuda_runtime.h>
#include <cuda_fp16.h>
#include <cstdint>
#include <cstddef>

#define CDIM 1024
#define HEADS 16
#define DHD 64
#define LSEQ 2048
#define BATCH 2
#define DFF 4096
#define NROWS (BATCH*LSEQ)   /* 4096 */

// ---------------- scratch (device globals: alloc-free) ----------------
__device__ float  g_ada[BATCH * 6 * CDIM];                  // [B,6,C]
__device__ float  g_qkv[(size_t)NROWS * 3 * CDIM];          // qkv f32 (pre-norm)
__device__ float  g_x1[(size_t)NROWS * CDIM];               // residual stream f32
__device__ __half g_wh[12582912];                           // converted weights
__device__ __half g_hh[(size_t)NROWS * CDIM];               // LN-mod out (half)
__device__ __half g_qkvh[(size_t)NROWS * 3 * CDIM];         // normalized qkv (half)
__device__ __half g_attnh[(size_t)NROWS * CDIM];            // attn out (half)
__device__ __half g_ffh[(size_t)NROWS * DFF];               // fc1+gelu out (half)

#define WH_QKV  0
#define WH_PROJ 3145728
#define WH_FC1  4194304
#define WH_FC2  8388608

// ================= helpers =================
__device__ __forceinline__ uint32_t smem_u32(const void* p) {
    uint32_t a;
    asm("{ .reg .u64 t; cvta.to.shared.u64 t, %1; cvt.u32.u64 %0, t; }" : "=r"(a) : "l"(p));
    return a;
}
__device__ __forceinline__ void cpasync16(uint32_t dst, const void* src) {
    asm volatile("cp.async.cg.shared.global [%0], [%1], 16;" :: "r"(dst), "l"(src));
}
__device__ __forceinline__ void cp_commit() { asm volatile("cp.async.commit_group;" ::: "memory"); }
__device__ __forceinline__ void cp_wait2()  { asm volatile("cp.async.wait_group 2;" ::: "memory"); }

__device__ __forceinline__ uint32_t f2h2(float x, float y) {
    __half2 h = __floats2half2_rn(x, y);
    return *reinterpret_cast<uint32_t*>(&h);
}
__device__ __forceinline__ void mma_f16(float* c,
    uint32_t a0, uint32_t a1, uint32_t a2, uint32_t a3, uint32_t b0, uint32_t b1)
{
    asm volatile(
        "mma.sync.aligned.m16n8k16.row.col.f32.f16.f16.f32 "
        "{%0,%1,%2,%3},{%4,%5,%6,%7},{%8,%9},{%0,%1,%2,%3};"
        : "+f"(c[0]), "+f"(c[1]), "+f"(c[2]), "+f"(c[3])
        : "r"(a0), "r"(a1), "r"(a2), "r"(a3), "r"(b0), "r"(b1));
}

// FMA-pipe exp (no MUFU)
__device__ __forceinline__ float fexp(float x) {
    float t = fmaxf(x, -87.f) * 1.4426950408889634f;
    float z = __fadd_rn(t, 12582912.0f);
    float n = __fsub_rn(z, 12582912.0f);
    int ni = (__float_as_int(z) & 0x7FFFFF) - 0x400000;
    float c = (t - n) * 0.6931471805599453f;
    float p = 8.3333333e-3f;
    p = fmaf(p, c, 4.1666667e-2f);
    p = fmaf(p, c, 0.16666667f);
    p = fmaf(p, c, 0.5f);
    p = fmaf(p, c, 1.0f);
    p = fmaf(p, c, 1.0f);
    return p * __int_as_float((ni + 127) << 23);
}

// ---------------- f32 -> f16 convert ----------------
__global__ __launch_bounds__(256) void f2h_kernel(
    const float4* __restrict__ src, uint2* __restrict__ dst, int n4)
{
    int i = blockIdx.x * 256 + threadIdx.x;
    if (i < n4) {
        float4 v = src[i];
        dst[i] = make_uint2(f2h2(v.x, v.y), f2h2(v.z, v.w));
    }
}

// ---------------- ada = silu(cond) @ ada_w.T + ada_b ----------------
__global__ __launch_bounds__(128) void ada_kernel(
    const float* __restrict__ cond, const float* __restrict__ ada_w,
    const float* __restrict__ ada_b)
{
    const int warp = threadIdx.x >> 5;
    const int lane = threadIdx.x & 31;
    const int o = blockIdx.x * 4 + warp;
    const int b = blockIdx.y;
    const float* wr = ada_w + (size_t)o * CDIM;
    const float* cr = cond + b * CDIM;
    float s = 0.f;
    for (int k = lane; k < CDIM; k += 32) {
        float c = cr[k];
        float si = c / (1.f + expf(-c));
        s += si * wr[k];
    }
    #pragma unroll
    for (int m = 16; m; m >>= 1) s += __shfl_xor_sync(0xffffffffu, s, m);
    if (lane == 0) g_ada[b * 6 * CDIM + o] = s + ada_b[o];
}

// ---------------- h = LN(x) * (scale+1) + shift  (half out) ----------------
__global__ __launch_bounds__(256) void ln_mod_kernel(
    const float* __restrict__ x, __half* __restrict__ h, int sc, int sh)
{
    __shared__ float red[2];
    const int row = blockIdx.x;
    const int b = row >> 11;
    const float* xr = x + (size_t)row * CDIM;
    float v[4];
    float s = 0.f, ss = 0.f;
    #pragma unroll
    for (int u = 0; u < 4; u++) {
        v[u] = xr[threadIdx.x + u * 256];
        s += v[u]; ss += v[u] * v[u];
    }
    #pragma unroll
    for (int m = 16; m; m >>= 1) {
        s  += __shfl_xor_sync(0xffffffffu, s, m);
        ss += __shfl_xor_sync(0xffffffffu, ss, m);
    }
    __shared__ float ws[16];
    int w = threadIdx.x >> 5, ln = threadIdx.x & 31;
    if (ln == 0) { ws[w] = s; ws[8 + w] = ss; }
    __syncthreads();
    if (threadIdx.x == 0) {
        float S = 0.f, SS = 0.f;
        #pragma unroll
        for (int i = 0; i < 8; i++) { S += ws[i]; SS += ws[8 + i]; }
        float m = S * (1.f / CDIM);
        float var = SS * (1.f / CDIM) - m * m;
        red[0] = m;
        red[1] = rsqrtf(var + 1e-6f);
    }
    __syncthreads();
    const float mean = red[0], rstd = red[1];
    const float* ap = g_ada + b * 6 * CDIM;
    #pragma unroll
    for (int u = 0; u < 4; u++) {
        int c = threadIdx.x + u * 256;
        float t = (v[u] - mean) * rstd * (ap[sc * CDIM + c] + 1.f) + ap[sh * CDIM + c];
        h[(size_t)row * CDIM + c] = __float2half_rn(t);
    }
}

// ================= fp16 mma.sync GEMM: C[M,N] = A[M,K] @ W[N,K]^T =================
// 128x128 CTA tile, BK=32 halfs, 4-stage cp.async, 8 warps (2x4), 64x32/warp.
#define TC_STAGES 4
#define TC_STR 40                              /* halfs per 32-elem row (+8 pad) */
#define TC_MAT_HALFS (128 * TC_STR)            /* 5120 */
#define TC_STAGE_BYTES (2 * TC_MAT_HALFS * 2)  /* 20480: A then B */
#define TC_SMEM (TC_STAGES * TC_STAGE_BYTES)   /* 81920 */

__global__ __launch_bounds__(256, 1)
void tc_gemm(int K, int N,
             const __half* __restrict__ A, const __half* __restrict__ W,
             const float* __restrict__ bias, void* __restrict__ Cout,
             const float* __restrict__ res, int gate_chunk, int act, int out_half)
{
    extern __shared__ __half smh[];
    const uint32_t sb = smem_u32(smh);
    const int tid = threadIdx.x;
    const int wid = tid >> 5, lane = tid & 31;
    const int wm = wid & 1, wn = wid >> 1;
    const int gid = lane >> 2, tig = lane & 3;
    const int m0 = blockIdx.y * 128, n0 = blockIdx.x * 128;
    const int NC = K >> 5;

    auto load_chunk = [&](int c) {
        const uint32_t base = sb + (c & (TC_STAGES - 1)) * TC_STAGE_BYTES;
        const int k0 = c << 5;
        #pragma unroll
        for (int t = 0; t < 2; t++) {
            int slot = tid + t * 256;        // 0..511
            int row = slot >> 2;             // 0..127
            int q = slot & 3;                // 16B chunk (8 halfs)
            uint32_t off = (uint32_t)(row * TC_STR + q * 8) * 2u;
            cpasync16(base + off, A + (size_t)(m0 + row) * K + k0 + q * 8);
            cpasync16(base + TC_MAT_HALFS * 2 + off, W + (size_t)(n0 + row) * K + k0 + q * 8);
        }
    };

    #pragma unroll
    for (int c = 0; c < TC_STAGES - 1; c++) { load_chunk(c); cp_commit(); }

    float acc[4][4][4];
    #pragma unroll
    for (int i = 0; i < 4; i++)
        #pragma unroll
        for (int j = 0; j < 4; j++)
            #pragma unroll
            for (int u = 0; u < 4; u++) acc[i][j][u] = 0.f;

    for (int c = 0; c < NC; c++) {
        cp_wait2();
        __syncthreads();
        const __half* sA = smh + (size_t)(c & (TC_STAGES - 1)) * (TC_STAGE_BYTES / 2);
        const __half* sB = sA + TC_MAT_HALFS;
        #pragma unroll
        for (int ks = 0; ks < 2; ks++) {
            const int k = ks * 16 + 2 * tig;
            uint32_t a[4][4];
            #pragma unroll
            for (int mt = 0; mt < 4; mt++) {
                const int r = wm * 64 + mt * 16 + gid;
                a[mt][0] = *(const uint32_t*)(sA + r * TC_STR + k);
                a[mt][1] = *(const uint32_t*)(sA + (r + 8) * TC_STR + k);
                a[mt][2] = *(const uint32_t*)(sA + r * TC_STR + k + 8);
                a[mt][3] = *(const uint32_t*)(sA + (r + 8) * TC_STR + k + 8);
            }
            uint32_t b[4][2];
            #pragma unroll
            for (int nt = 0; nt < 4; nt++) {
                const int r = wn * 32 + nt * 8 + gid;
                b[nt][0] = *(const uint32_t*)(sB + r * TC_STR + k);
                b[nt][1] = *(const uint32_t*)(sB + r * TC_STR + k + 8);
            }
            #pragma unroll
            for (int mt = 0; mt < 4; mt++)
                #pragma unroll
                for (int nt = 0; nt < 4; nt++)
                    mma_f16(acc[mt][nt], a[mt][0], a[mt][1], a[mt][2], a[mt][3],
                            b[nt][0], b[nt][1]);
        }
        __syncthreads();
        if (c + TC_STAGES - 1 < NC) load_chunk(c + TC_STAGES - 1);
        cp_commit();
    }

    // ---- fused epilogue ----
    #pragma unroll
    for (int mt = 0; mt < 4; mt++) {
        #pragma unroll
        for (int half_i = 0; half_i < 2; half_i++) {
            const int m = m0 + wm * 64 + mt * 16 + gid + half_i * 8;
            const int bb = m >> 11;
            const float* ap = g_ada + bb * 6 * CDIM;
            #pragma unroll
            for (int nt = 0; nt < 4; nt++) {
                const int n = n0 + wn * 32 + nt * 8 + tig * 2;
                float v0 = acc[mt][nt][half_i * 2];
                float v1 = acc[mt][nt][half_i * 2 + 1];
                if (bias) { v0 += bias[n]; v1 += bias[n + 1]; }
                if (act == 1) {
                    float t3 = v0 * v0 * v0;
                    v0 = 0.5f * v0 * (1.f + tanhf(0.7978845608028654f * (v0 + 0.044715f * t3)));
                    t3 = v1 * v1 * v1;
                    v1 = 0.5f * v1 * (1.f + tanhf(0.7978845608028654f * (v1 + 0.044715f * t3)));
                }
                if (gate_chunk >= 0) {
                    v0 *= ap[gate_chunk * CDIM + n];
                    v1 *= ap[gate_chunk * CDIM + n + 1];
                }
                if (res) {
                    v0 += res[(size_t)m * N + n];
                    v1 += res[(size_t)m * N + n + 1];
                }
                if (out_half) {
                    *(uint32_t*)((__half*)Cout + (size_t)m * N + n) = f2h2(v0, v1);
                } else {
                    *(float2*)((float*)Cout + (size_t)m * N + n) = make_float2(v0, v1);
                }
            }
        }
    }
}

// ---------------- qkv norm: bias + L2-normalize q/k + scale; emit half ----------------
__global__ __launch_bounds__(256) void qkv_norm_kernel(
    const float* __restrict__ q_bias, const float* __restrict__ v_bias,
    const float* __restrict__ scale_mul)
{
    const int gw = blockIdx.x * 8 + (threadIdx.x >> 5);
    const int lane = threadIdx.x & 31;
    const int h = gw & 15;
    const int t = (gw >> 4) % 3;
    const int bl = gw / 48;
    const size_t off = ((size_t)bl * 3 + t) * CDIM + h * DHD;
    const float* p = g_qkv + off;
    float v0 = p[lane], v1 = p[lane + 32];
    if (t == 0) { v0 += q_bias[h * DHD + lane]; v1 += q_bias[h * DHD + lane + 32]; }
    else if (t == 2) { v0 += v_bias[h * DHD + lane]; v1 += v_bias[h * DHD + lane + 32]; }
    if (t < 2) {
        float ss = v0 * v0 + v1 * v1;
        #pragma unroll
        for (int m = 16; m; m >>= 1) ss += __shfl_xor_sync(0xffffffffu, ss, m);
        float r = rsqrtf(fmaxf(ss, 1e-24f));
        if (t == 0) r *= expf(fminf(scale_mul[h], 4.605170185988092f));
        v0 *= r; v1 *= r;
    }
    g_qkvh[off + lane] = __float2half_rn(v0);
    g_qkvh[off + lane + 32] = __float2half_rn(v1);
}

// ================= flash attention, fp16 mma =================
#define FA_STR 72                                  /* halfs per row */
#define FA_SQ   (128 * FA_STR)
#define FA_SK   (64 * FA_STR)
#define FA_SMEM ((FA_SQ + 2 * FA_SK + 8 * 16 * FA_STR) * 2)   /* 55296 B */

__global__ __launch_bounds__(256, 1)
void flash_mma(const float* __restrict__ abias, __half* __restrict__ out)
{
    extern __shared__ __half fsm[];
    __half* sQ  = fsm;                      // [128][72]
    __half* sK  = sQ + FA_SQ;               // [64][72]  (kcol, d)
    __half* sVT = sK + FA_SK;               // [64][72]  (d, kcol)
    __half* sP  = sVT + FA_SK;              // 8 x [16][72]

    const int qt = blockIdx.x, bh = blockIdx.y;
    const int b = bh >> 4, h = bh & 15;
    const int tid = threadIdx.x, wid = tid >> 5, lane = tid & 31;
    const int gid = lane >> 2, tig = lane & 3;
    __half* sPw = sP + wid * 16 * FA_STR;
    const int qrow0 = qt * 128;
    const int wq0 = wid * 16;

    // load Q tile (half, 16B chunks)
    for (int i = tid; i < 128 * 8; i += 256) {
        int r = i >> 3, c8 = i & 7;
        uint4 v = *(const uint4*)(g_qkvh +
            ((size_t)(b * LSEQ + qrow0 + r) * 3 + 0) * CDIM + h * DHD + c8 * 8);
        *(uint4*)(sQ + r * FA_STR + c8 * 8) = v;
    }

    float oacc[8][4];
    #pragma unroll
    for (int i = 0; i < 8; i++)
        #pragma unroll
        for (int j = 0; j < 4; j++) oacc[i][j] = 0.f;
    float m0r = -1e30f, m1r = -1e30f, l0 = 0.f, l1 = 0.f;

    for (int kt = 0; kt < LSEQ / 64; kt++) {
        __syncthreads();
        for (int i = tid; i < 64 * 8; i += 256) {
            int r = i >> 3, c8 = i & 7;
            uint4 v = *(const uint4*)(g_qkvh +
                ((size_t)(b * LSEQ + kt * 64 + r) * 3 + 1) * CDIM + h * DHD + c8 * 8);
            *(uint4*)(sK + r * FA_STR + c8 * 8) = v;
            uint4 w = *(const uint4*)(g_qkvh +
                ((size_t)(b * LSEQ + kt * 64 + r) * 3 + 2) * CDIM + h * DHD + c8 * 8);
            const __half* wh = (const __half*)&w;
            int c0 = c8 * 8;
            #pragma unroll
            for (int j = 0; j < 8; j++) sVT[(c0 + j) * FA_STR + r] = wh[j];
        }
        __syncthreads();

        // S = Q K^T
        float sacc[8][4];
        #pragma unroll
        for (int i = 0; i < 8; i++)
            #pragma unroll
            for (int j = 0; j < 4; j++) sacc[i][j] = 0.f;
        #pragma unroll
        for (int ks = 0; ks < 4; ks++) {
            const int k = ks * 16 + 2 * tig;
            uint32_t a0 = *(const uint32_t*)(sQ + (wq0 + gid) * FA_STR + k);
            uint32_t a1 = *(const uint32_t*)(sQ + (wq0 + gid + 8) * FA_STR + k);
            uint32_t a2 = *(const uint32_t*)(sQ + (wq0 + gid) * FA_STR + k + 8);
            uint32_t a3 = *(const uint32_t*)(sQ + (wq0 + gid + 8) * FA_STR + k + 8);
            #pragma unroll
            for (int nt = 0; nt < 8; nt++) {
                uint32_t b0 = *(const uint32_t*)(sK + (nt * 8 + gid) * FA_STR + k);
                uint32_t b1 = *(const uint32_t*)(sK + (nt * 8 + gid) * FA_STR + k + 8);
                mma_f16(sacc[nt], a0, a1, a2, a3, b0, b1);
            }
        }
        // + attn_bias
        {
            const float* bp = abias + (size_t)(qrow0 + wq0) * LSEQ + kt * 64;
            #pragma unroll
            for (int nt = 0; nt < 8; nt++) {
                float2 b01 = *(const float2*)(bp + (size_t)gid * LSEQ + nt * 8 + 2 * tig);
                float2 b23 = *(const float2*)(bp + (size_t)(gid + 8) * LSEQ + nt * 8 + 2 * tig);
                sacc[nt][0] += b01.x; sacc[nt][1] += b01.y;
                sacc[nt][2] += b23.x; sacc[nt][3] += b23.y;
            }
        }
        // online softmax
        float mx0 = -1e30f, mx1 = -1e30f;
        #pragma unroll
        for (int nt = 0; nt < 8; nt++) {
            mx0 = fmaxf(mx0, fmaxf(sacc[nt][0], sacc[nt][1]));
            mx1 = fmaxf(mx1, fmaxf(sacc[nt][2], sacc[nt][3]));
        }
        mx0 = fmaxf(mx0, __shfl_xor_sync(0xffffffffu, mx0, 1));
        mx0 = fmaxf(mx0, __shfl_xor_sync(0xffffffffu, mx0, 2));
        mx1 = fmaxf(mx1, __shfl_xor_sync(0xffffffffu, mx1, 1));
        mx1 = fmaxf(mx1, __shfl_xor_sync(0xffffffffu, mx1, 2));
        float mn0 = fmaxf(m0r, mx0), mn1 = fmaxf(m1r, mx1);
        float al0 = fexp(m0r - mn0), al1 = fexp(m1r - mn1);
        float rs0 = 0.f, rs1 = 0.f;
        #pragma unroll
        for (int nt = 0; nt < 8; nt++) {
            sacc[nt][0] = fexp(sacc[nt][0] - mn0);
            sacc[nt][1] = fexp(sacc[nt][1] - mn0);
            sacc[nt][2] = fexp(sacc[nt][2] - mn1);
            sacc[nt][3] = fexp(sacc[nt][3] - mn1);
            rs0 += sacc[nt][0] + sacc[nt][1];
            rs1 += sacc[nt][2] + sacc[nt][3];
        }
        rs0 += __shfl_xor_sync(0xffffffffu, rs0, 1);
        rs0 += __shfl_xor_sync(0xffffffffu, rs0, 2);
        rs1 += __shfl_xor_sync(0xffffffffu, rs1, 1);
        rs1 += __shfl_xor_sync(0xffffffffu, rs1, 2);
        l0 = l0 * al0 + rs0; l1 = l1 * al1 + rs1;
        m0r = mn0; m1r = mn1;
        #pragma unroll
        for (int dt = 0; dt < 8; dt++) {
            oacc[dt][0] *= al0; oacc[dt][1] *= al0;
            oacc[dt][2] *= al1; oacc[dt][3] *= al1;
        }
        // P (half) -> warp-private smem
        #pragma unroll
        for (int nt = 0; nt < 8; nt++) {
            *(uint32_t*)(sPw + gid * FA_STR + nt * 8 + 2 * tig) =
                f2h2(sacc[nt][0], sacc[nt][1]);
            *(uint32_t*)(sPw + (gid + 8) * FA_STR + nt * 8 + 2 * tig) =
                f2h2(sacc[nt][2], sacc[nt][3]);
        }
        __syncwarp();
        // O += P V
        #pragma unroll
        for (int kc = 0; kc < 4; kc++) {
            const int k = kc * 16 + 2 * tig;
            uint32_t a0 = *(const uint32_t*)(sPw + gid * FA_STR + k);
            uint32_t a1 = *(const uint32_t*)(sPw + (gid + 8) * FA_STR + k);
            uint32_t a2 = *(const uint32_t*)(sPw + gid * FA_STR + k + 8);
            uint32_t a3 = *(const uint32_t*)(sPw + (gid + 8) * FA_STR + k + 8);
            #pragma unroll
            for (int dt = 0; dt < 8; dt++) {
                uint32_t b0 = *(const uint32_t*)(sVT + (dt * 8 + gid) * FA_STR + k);
                uint32_t b1 = *(const uint32_t*)(sVT + (dt * 8 + gid) * FA_STR + k + 8);
                mma_f16(oacc[dt], a0, a1, a2, a3, b0, b1);
            }
        }
    }
    // write O / l  (half) to [B*L, C]
    {
        float inv0 = 1.f / l0, inv1 = 1.f / l1;
        const size_t r0 = (size_t)(b * LSEQ + qrow0 + wq0 + gid);
        const size_t r1 = r0 + 8;
        #pragma unroll
        for (int dt = 0; dt < 8; dt++) {
            int col = h * DHD + dt * 8 + 2 * tig;
            *(uint32_t*)(out + r0 * CDIM + col) = f2h2(oacc[dt][0] * inv0, oacc[dt][1] * inv0);
            *(uint32_t*)(out + r1 * CDIM + col) = f2h2(oacc[dt][2] * inv1, oacc[dt][3] * inv1);
        }
    }
}

// ---------------- launch ----------------
extern "C" void kernel_launch(void* const* d_in, const int* in_sizes, int n_in,
                              void* d_out, int out_size)
{
    const float* x         = (const float*)d_in[0];
    const float* cond_BD   = (const float*)d_in[1];
    const float* attn_bias = (const float*)d_in[2];
    const float* qkv_w     = (const float*)d_in[3];
    const float* q_bias    = (const float*)d_in[4];
    const float* v_bias    = (const float*)d_in[5];
    const float* scale_mul = (const float*)d_in[6];
    const float* proj_w    = (const float*)d_in[7];
    const float* proj_b    = (const float*)d_in[8];
    const float* fc1_w     = (const float*)d_in[9];
    const float* fc1_b     = (const float*)d_in[10];
    const float* fc2_w     = (const float*)d_in[11];
    const float* fc2_b     = (const float*)d_in[12];
    const float* ada_w     = (const float*)d_in[13];
    const float* ada_b     = (const float*)d_in[14];
    float* outp = (float*)d_out;

    float *p_qkv, *p_x1;
    __half *p_wh, *p_hh, *p_qkvh, *p_attnh, *p_ffh;
    cudaGetSymbolAddress((void**)&p_qkv, g_qkv);
    cudaGetSymbolAddress((void**)&p_x1, g_x1);
    cudaGetSymbolAddress((void**)&p_wh, g_wh);
    cudaGetSymbolAddress((void**)&p_hh, g_hh);
    cudaGetSymbolAddress((void**)&p_qkvh, g_qkvh);
    cudaGetSymbolAddress((void**)&p_attnh, g_attnh);
    cudaGetSymbolAddress((void**)&p_ffh, g_ffh);

    cudaFuncSetAttribute(tc_gemm, cudaFuncAttributeMaxDynamicSharedMemorySize, TC_SMEM);
    cudaFuncSetAttribute(flash_mma, cudaFuncAttributeMaxDynamicSharedMemorySize, FA_SMEM);

    // 0) weight conversions (f32 -> f16)
    f2h_kernel<<<(3*CDIM*CDIM/4 + 255)/256, 256>>>((const float4*)qkv_w, (uint2*)(p_wh + WH_QKV), 3*CDIM*CDIM/4);
    f2h_kernel<<<(CDIM*CDIM/4 + 255)/256, 256>>>((const float4*)proj_w, (uint2*)(p_wh + WH_PROJ), CDIM*CDIM/4);
    f2h_kernel<<<(DFF*CDIM/4 + 255)/256, 256>>>((const float4*)fc1_w, (uint2*)(p_wh + WH_FC1), DFF*CDIM/4);
    f2h_kernel<<<(CDIM*DFF/4 + 255)/256, 256>>>((const float4*)fc2_w, (uint2*)(p_wh + WH_FC2), CDIM*DFF/4);

    // 1) adaLN coefficients
    ada_kernel<<<dim3(6 * CDIM / 4, BATCH), 128>>>(cond_BD, ada_w, ada_b);
    // 2) h = LN(x)*(s1+1)+sh1   (chunks: g1=0,g2=1,s1=2,s2=3,sh1=4,sh2=5)
    ln_mod_kernel<<<NROWS, 256>>>(x, p_hh, 2, 4);
    // 3) qkv = h @ qkv_w^T  (f32 out)
    tc_gemm<<<dim3(3 * CDIM / 128, NROWS / 128), 256, TC_SMEM>>>(
        CDIM, 3 * CDIM, p_hh, p_wh + WH_QKV, nullptr, p_qkv, nullptr, -1, 0, 0);
    // 4) bias + per-head L2 norm + scale -> half
    qkv_norm_kernel<<<NROWS * 3 * HEADS / 8, 256>>>(q_bias, v_bias, scale_mul);
    // 5) attention (fp16 mma) -> half
    flash_mma<<<dim3(LSEQ / 128, BATCH * HEADS), 256, FA_SMEM>>>(attn_bias, p_attnh);
    // 6) x1 = x + (attn @ proj_w^T + proj_b) * g1  (f32 out)
    tc_gemm<<<dim3(CDIM / 128, NROWS / 128), 256, TC_SMEM>>>(
        CDIM, CDIM, p_attnh, p_wh + WH_PROJ, proj_b, p_x1, x, 0, 0, 0);
    // 7) h = LN(x1)*(s2+1)+sh2
    ln_mod_kernel<<<NROWS, 256>>>(p_x1, p_hh, 3, 5);
    // 8) ff = gelu(h @ fc1_w^T + fc1_b)  (half out)
    tc_gemm<<<dim3(DFF / 128, NROWS / 128), 256, TC_SMEM>>>(
        CDIM, DFF, p_hh, p_wh + WH_FC1, fc1_b, p_ffh, nullptr, -1, 1, 1);
    // 9) out = x1 + (ff @ fc2_w^T + fc2_b) * g2  (f32 out)
    tc_gemm<<<dim3(CDIM / 128, NROWS / 128), 256, TC_SMEM>>>(
        DFF, CDIM, p_ffh, p_wh + WH_FC2, fc2_b, outp, p_x1, 1, 0, 0);
}

// round 8
// speedup vs baseline: 5.8823x; 1.4855x over previous
#include <cuda_runtime.h>
#include <cuda_fp16.h>
#include <cstdint>
#include <cstddef>

#define CDIM 1024
#define HEADS 16
#define DHD 64
#define LSEQ 2048
#define BATCH 2
#define DFF 4096
#define NROWS (BATCH*LSEQ)   /* 4096 */

// ---------------- scratch (device globals: alloc-free) ----------------
__device__ float  g_ada[BATCH * 6 * CDIM];                  // [B,6,C]
__device__ float  g_qkv[(size_t)NROWS * 3 * CDIM];          // qkv f32 (pre-norm)
__device__ float  g_x1[(size_t)NROWS * CDIM];               // residual stream f32
__device__ __half g_wh[12582912];                           // converted weights
__device__ __half g_hh[(size_t)NROWS * CDIM];               // LN-mod out (half)
__device__ __half g_qkvh[(size_t)NROWS * 3 * CDIM];         // normalized qkv (half)
__device__ __half g_attnh[(size_t)NROWS * CDIM];            // attn out (half)
__device__ __half g_ffh[(size_t)NROWS * DFF];               // fc1+gelu out (half)

#define WH_QKV  0
#define WH_PROJ 3145728
#define WH_FC1  4194304
#define WH_FC2  8388608

// ================= helpers =================
__device__ __forceinline__ uint32_t smem_u32(const void* p) {
    uint32_t a;
    asm("{ .reg .u64 t; cvta.to.shared.u64 t, %1; cvt.u32.u64 %0, t; }" : "=r"(a) : "l"(p));
    return a;
}
__device__ __forceinline__ void cpasync16(uint32_t dst, const void* src) {
    asm volatile("cp.async.cg.shared.global [%0], [%1], 16;" :: "r"(dst), "l"(src));
}
__device__ __forceinline__ void cp_commit() { asm volatile("cp.async.commit_group;" ::: "memory"); }
__device__ __forceinline__ void cp_wait2()  { asm volatile("cp.async.wait_group 2;" ::: "memory"); }
__device__ __forceinline__ void cp_wait1()  { asm volatile("cp.async.wait_group 1;" ::: "memory"); }

__device__ __forceinline__ uint32_t f2h2(float x, float y) {
    __half2 h = __floats2half2_rn(x, y);
    return *reinterpret_cast<uint32_t*>(&h);
}
__device__ __forceinline__ void mma_f16(float* c,
    uint32_t a0, uint32_t a1, uint32_t a2, uint32_t a3, uint32_t b0, uint32_t b1)
{
    asm volatile(
        "mma.sync.aligned.m16n8k16.row.col.f32.f16.f16.f32 "
        "{%0,%1,%2,%3},{%4,%5,%6,%7},{%8,%9},{%0,%1,%2,%3};"
        : "+f"(c[0]), "+f"(c[1]), "+f"(c[2]), "+f"(c[3])
        : "r"(a0), "r"(a1), "r"(a2), "r"(a3), "r"(b0), "r"(b1));
}
__device__ __forceinline__ void ldsm_x4(uint32_t& r0, uint32_t& r1, uint32_t& r2, uint32_t& r3,
                                        uint32_t addr) {
    asm volatile("ldmatrix.sync.aligned.m8n8.x4.shared.b16 {%0,%1,%2,%3}, [%4];"
        : "=r"(r0), "=r"(r1), "=r"(r2), "=r"(r3) : "r"(addr));
}
__device__ __forceinline__ void ldsm_x4_t(uint32_t& r0, uint32_t& r1, uint32_t& r2, uint32_t& r3,
                                          uint32_t addr) {
    asm volatile("ldmatrix.sync.aligned.m8n8.x4.trans.shared.b16 {%0,%1,%2,%3}, [%4];"
        : "=r"(r0), "=r"(r1), "=r"(r2), "=r"(r3) : "r"(addr));
}

// FMA-pipe exp (no MUFU)
__device__ __forceinline__ float fexp(float x) {
    float t = fmaxf(x, -87.f) * 1.4426950408889634f;
    float z = __fadd_rn(t, 12582912.0f);
    float n = __fsub_rn(z, 12582912.0f);
    int ni = (__float_as_int(z) & 0x7FFFFF) - 0x400000;
    float c = (t - n) * 0.6931471805599453f;
    float p = 8.3333333e-3f;
    p = fmaf(p, c, 4.1666667e-2f);
    p = fmaf(p, c, 0.16666667f);
    p = fmaf(p, c, 0.5f);
    p = fmaf(p, c, 1.0f);
    p = fmaf(p, c, 1.0f);
    return p * __int_as_float((ni + 127) << 23);
}

// ---------------- f32 -> f16 convert ----------------
__global__ __launch_bounds__(256) void f2h_kernel(
    const float4* __restrict__ src, uint2* __restrict__ dst, int n4)
{
    int i = blockIdx.x * 256 + threadIdx.x;
    if (i < n4) {
        float4 v = src[i];
        dst[i] = make_uint2(f2h2(v.x, v.y), f2h2(v.z, v.w));
    }
}

// ---------------- ada = silu(cond) @ ada_w.T + ada_b ----------------
__global__ __launch_bounds__(128) void ada_kernel(
    const float* __restrict__ cond, const float* __restrict__ ada_w,
    const float* __restrict__ ada_b)
{
    const int warp = threadIdx.x >> 5;
    const int lane = threadIdx.x & 31;
    const int o = blockIdx.x * 4 + warp;
    const int b = blockIdx.y;
    const float* wr = ada_w + (size_t)o * CDIM;
    const float* cr = cond + b * CDIM;
    float s = 0.f;
    for (int k = lane; k < CDIM; k += 32) {
        float c = cr[k];
        float si = c / (1.f + expf(-c));
        s += si * wr[k];
    }
    #pragma unroll
    for (int m = 16; m; m >>= 1) s += __shfl_xor_sync(0xffffffffu, s, m);
    if (lane == 0) g_ada[b * 6 * CDIM + o] = s + ada_b[o];
}

// ---------------- h = LN(x) * (scale+1) + shift  (half out) ----------------
__global__ __launch_bounds__(256) void ln_mod_kernel(
    const float* __restrict__ x, __half* __restrict__ h, int sc, int sh)
{
    __shared__ float red[2];
    const int row = blockIdx.x;
    const int b = row >> 11;
    const float* xr = x + (size_t)row * CDIM;
    float v[4];
    float s = 0.f, ss = 0.f;
    #pragma unroll
    for (int u = 0; u < 4; u++) {
        v[u] = xr[threadIdx.x + u * 256];
        s += v[u]; ss += v[u] * v[u];
    }
    #pragma unroll
    for (int m = 16; m; m >>= 1) {
        s  += __shfl_xor_sync(0xffffffffu, s, m);
        ss += __shfl_xor_sync(0xffffffffu, ss, m);
    }
    __shared__ float ws[16];
    int w = threadIdx.x >> 5, ln = threadIdx.x & 31;
    if (ln == 0) { ws[w] = s; ws[8 + w] = ss; }
    __syncthreads();
    if (threadIdx.x == 0) {
        float S = 0.f, SS = 0.f;
        #pragma unroll
        for (int i = 0; i < 8; i++) { S += ws[i]; SS += ws[8 + i]; }
        float m = S * (1.f / CDIM);
        float var = SS * (1.f / CDIM) - m * m;
        red[0] = m;
        red[1] = rsqrtf(var + 1e-6f);
    }
    __syncthreads();
    const float mean = red[0], rstd = red[1];
    const float* ap = g_ada + b * 6 * CDIM;
    #pragma unroll
    for (int u = 0; u < 4; u++) {
        int c = threadIdx.x + u * 256;
        float t = (v[u] - mean) * rstd * (ap[sc * CDIM + c] + 1.f) + ap[sh * CDIM + c];
        h[(size_t)row * CDIM + c] = __float2half_rn(t);
    }
}

// ================= fp16 mma.sync GEMM: C[M,N] = A[M,K] @ W[N,K]^T =================
// 128x128 CTA tile, BK=32 halfs, 4-stage cp.async, 8 warps (2x4), ldmatrix frags.
#define TC_STAGES 4
#define TC_STR 40                              /* halfs per 32-elem row (+8 pad) */
#define TC_MAT_HALFS (128 * TC_STR)            /* 5120 */
#define TC_STAGE_BYTES (2 * TC_MAT_HALFS * 2)  /* 20480: A then B */
#define TC_SMEM (TC_STAGES * TC_STAGE_BYTES)   /* 81920 */

__global__ __launch_bounds__(256, 2)
void tc_gemm(int K, int N,
             const __half* __restrict__ A, const __half* __restrict__ W,
             const float* __restrict__ bias, void* __restrict__ Cout,
             const float* __restrict__ res, int gate_chunk, int act, int out_half)
{
    extern __shared__ __half smh[];
    const uint32_t sb = smem_u32(smh);
    const int tid = threadIdx.x;
    const int wid = tid >> 5, lane = tid & 31;
    const int wm = wid & 1, wn = wid >> 1;
    const int gid = lane >> 2, tig = lane & 3;
    const int m0 = blockIdx.y * 128, n0 = blockIdx.x * 128;
    const int NC = K >> 5;

    auto load_chunk = [&](int c) {
        const uint32_t base = sb + (c & (TC_STAGES - 1)) * TC_STAGE_BYTES;
        const int k0 = c << 5;
        #pragma unroll
        for (int t = 0; t < 2; t++) {
            int slot = tid + t * 256;        // 0..511
            int row = slot >> 2;             // 0..127
            int q = slot & 3;                // 16B chunk (8 halfs)
            uint32_t off = (uint32_t)(row * TC_STR + q * 8) * 2u;
            cpasync16(base + off, A + (size_t)(m0 + row) * K + k0 + q * 8);
            cpasync16(base + TC_MAT_HALFS * 2 + off, W + (size_t)(n0 + row) * K + k0 + q * 8);
        }
    };

    #pragma unroll
    for (int c = 0; c < TC_STAGES - 1; c++) { load_chunk(c); cp_commit(); }

    float acc[4][4][4];
    #pragma unroll
    for (int i = 0; i < 4; i++)
        #pragma unroll
        for (int j = 0; j < 4; j++)
            #pragma unroll
            for (int u = 0; u < 4; u++) acc[i][j][u] = 0.f;

    // ldmatrix lane address components
    const int la_row = (lane & 7) + ((lane >> 3) & 1) * 8;   // A: row offset, k group = lane>>4
    const int la_kk  = (lane >> 4) * 8;
    const int lb_row = ((lane >> 4) & 1) * 8 + (lane & 7);   // B: row uses bit4, k uses bit3
    const int lb_kk  = ((lane >> 3) & 1) * 8;

    for (int c = 0; c < NC; c++) {
        cp_wait2();
        __syncthreads();
        const uint32_t sA = sb + (uint32_t)(c & (TC_STAGES - 1)) * TC_STAGE_BYTES;
        const uint32_t sB = sA + TC_MAT_HALFS * 2;
        #pragma unroll
        for (int ks = 0; ks < 2; ks++) {
            uint32_t a[4][4], bf[4][2];
            #pragma unroll
            for (int mt = 0; mt < 4; mt++) {
                int row = wm * 64 + mt * 16 + la_row;
                ldsm_x4(a[mt][0], a[mt][1], a[mt][2], a[mt][3],
                        sA + (uint32_t)(row * TC_STR + ks * 16 + la_kk) * 2);
            }
            #pragma unroll
            for (int ntp = 0; ntp < 2; ntp++) {
                int row = wn * 32 + ntp * 16 + lb_row;
                ldsm_x4(bf[2 * ntp][0], bf[2 * ntp][1], bf[2 * ntp + 1][0], bf[2 * ntp + 1][1],
                        sB + (uint32_t)(row * TC_STR + ks * 16 + lb_kk) * 2);
            }
            #pragma unroll
            for (int mt = 0; mt < 4; mt++)
                #pragma unroll
                for (int nt = 0; nt < 4; nt++)
                    mma_f16(acc[mt][nt], a[mt][0], a[mt][1], a[mt][2], a[mt][3],
                            bf[nt][0], bf[nt][1]);
        }
        __syncthreads();
        if (c + TC_STAGES - 1 < NC) load_chunk(c + TC_STAGES - 1);
        cp_commit();
    }

    // ---- fused epilogue ----
    #pragma unroll
    for (int mt = 0; mt < 4; mt++) {
        #pragma unroll
        for (int half_i = 0; half_i < 2; half_i++) {
            const int m = m0 + wm * 64 + mt * 16 + gid + half_i * 8;
            const int bb = m >> 11;
            const float* ap = g_ada + bb * 6 * CDIM;
            #pragma unroll
            for (int nt = 0; nt < 4; nt++) {
                const int n = n0 + wn * 32 + nt * 8 + tig * 2;
                float v0 = acc[mt][nt][half_i * 2];
                float v1 = acc[mt][nt][half_i * 2 + 1];
                if (bias) { v0 += bias[n]; v1 += bias[n + 1]; }
                if (act == 1) {
                    float t3 = v0 * v0 * v0;
                    v0 = 0.5f * v0 * (1.f + tanhf(0.7978845608028654f * (v0 + 0.044715f * t3)));
                    t3 = v1 * v1 * v1;
                    v1 = 0.5f * v1 * (1.f + tanhf(0.7978845608028654f * (v1 + 0.044715f * t3)));
                }
                if (gate_chunk >= 0) {
                    v0 *= ap[gate_chunk * CDIM + n];
                    v1 *= ap[gate_chunk * CDIM + n + 1];
                }
                if (res) {
                    v0 += res[(size_t)m * N + n];
                    v1 += res[(size_t)m * N + n + 1];
                }
                if (out_half) {
                    *(uint32_t*)((__half*)Cout + (size_t)m * N + n) = f2h2(v0, v1);
                } else {
                    *(float2*)((float*)Cout + (size_t)m * N + n) = make_float2(v0, v1);
                }
            }
        }
    }
}

// ---------------- qkv norm: bias + L2-normalize q/k + scale; emit half ----------------
__global__ __launch_bounds__(256) void qkv_norm_kernel(
    const float* __restrict__ q_bias, const float* __restrict__ v_bias,
    const float* __restrict__ scale_mul)
{
    const int gw = blockIdx.x * 8 + (threadIdx.x >> 5);
    const int lane = threadIdx.x & 31;
    const int h = gw & 15;
    const int t = (gw >> 4) % 3;
    const int bl = gw / 48;
    const size_t off = ((size_t)bl * 3 + t) * CDIM + h * DHD;
    const float* p = g_qkv + off;
    float v0 = p[lane], v1 = p[lane + 32];
    if (t == 0) { v0 += q_bias[h * DHD + lane]; v1 += q_bias[h * DHD + lane + 32]; }
    else if (t == 2) { v0 += v_bias[h * DHD + lane]; v1 += v_bias[h * DHD + lane + 32]; }
    if (t < 2) {
        float ss = v0 * v0 + v1 * v1;
        #pragma unroll
        for (int m = 16; m; m >>= 1) ss += __shfl_xor_sync(0xffffffffu, ss, m);
        float r = rsqrtf(fmaxf(ss, 1e-24f));
        if (t == 0) r *= expf(fminf(scale_mul[h], 4.605170185988092f));
        v0 *= r; v1 *= r;
    }
    g_qkvh[off + lane] = __float2half_rn(v0);
    g_qkvh[off + lane + 32] = __float2half_rn(v1);
}

// ================= flash attention, fp16 mma, ldmatrix + fragment chaining =================
#define FA_STR 72                                  /* halfs per row */
#define FA_SQ   (128 * FA_STR)
#define FA_SK   (64 * FA_STR)                      /* per stage */
#define FA_SMEM ((FA_SQ + 4 * FA_SK) * 2)          /* Q + 2-stage K + 2-stage V = 55296 B */

__global__ __launch_bounds__(256, 2)
void flash_mma(const float* __restrict__ abias, __half* __restrict__ out)
{
    extern __shared__ __half fsm[];
    const uint32_t sqb = smem_u32(fsm);             // sQ  [128][72]
    const uint32_t skb = sqb + FA_SQ * 2;           // sK  2 x [64][72]
    const uint32_t svb = skb + 2 * FA_SK * 2;       // sV  2 x [64][72] (natural [kcol][d])

    const int qt = blockIdx.x, bh = blockIdx.y;
    const int b = bh >> 4, h = bh & 15;
    const int tid = threadIdx.x, wid = tid >> 5, lane = tid & 31;
    const int gid = lane >> 2, tig = lane & 3;
    const int qrow0 = qt * 128;
    const int wq0 = wid * 16;

    // ldmatrix lane address components
    const int la_row = (lane & 7) + ((lane >> 3) & 1) * 8;
    const int la_kk  = (lane >> 4) * 8;
    const int lb_row = ((lane >> 4) & 1) * 8 + (lane & 7);
    const int lb_kk  = ((lane >> 3) & 1) * 8;

    // load Q tile (synchronous, once)
    for (int i = tid; i < 128 * 8; i += 256) {
        int r = i >> 3, c8 = i & 7;
        uint4 v = *(const uint4*)(g_qkvh +
            ((size_t)(b * LSEQ + qrow0 + r) * 3 + 0) * CDIM + h * DHD + c8 * 8);
        *(uint4*)(fsm + r * FA_STR + c8 * 8) = v;
    }

    // cp.async K+V (natural layout) for ktile kt into stage kt&1
    auto load_kv = [&](int kt) {
        const uint32_t st = (uint32_t)(kt & 1) * FA_SK * 2;
        #pragma unroll
        for (int t = 0; t < 2; t++) {
            int slot = tid + t * 256;       // 0..511
            int r = slot >> 3, c8 = slot & 7;
            const __half* kp = g_qkvh +
                ((size_t)(b * LSEQ + kt * 64 + r) * 3 + 1) * CDIM + h * DHD + c8 * 8;
            uint32_t off = (uint32_t)(r * FA_STR + c8 * 8) * 2u;
            cpasync16(skb + st + off, kp);
            cpasync16(svb + st + off, kp + CDIM);   // V plane = K plane + CDIM
        }
    };

    load_kv(0); cp_commit();

    float oacc[8][4];
    #pragma unroll
    for (int i = 0; i < 8; i++)
        #pragma unroll
        for (int j = 0; j < 4; j++) oacc[i][j] = 0.f;
    float m0r = -1e30f, m1r = -1e30f, l0 = 0.f, l1 = 0.f;

    const int NT = LSEQ / 64;
    for (int kt = 0; kt < NT; kt++) {
        __syncthreads();                         // prior compute done before overwriting stage
        if (kt + 1 < NT) load_kv(kt + 1);
        cp_commit();
        cp_wait1();                              // stage kt resident
        __syncthreads();

        const uint32_t sKst = skb + (uint32_t)(kt & 1) * FA_SK * 2;
        const uint32_t sVst = svb + (uint32_t)(kt & 1) * FA_SK * 2;

        // S = Q K^T  (16 x 64 per warp)
        float sacc[8][4];
        #pragma unroll
        for (int i = 0; i < 8; i++)
            #pragma unroll
            for (int j = 0; j < 4; j++) sacc[i][j] = 0.f;
        #pragma unroll
        for (int ks = 0; ks < 4; ks++) {
            uint32_t a0, a1, a2, a3;
            ldsm_x4(a0, a1, a2, a3,
                sqb + (uint32_t)((wq0 + la_row) * FA_STR + ks * 16 + la_kk) * 2);
            #pragma unroll
            for (int ntp = 0; ntp < 4; ntp++) {
                uint32_t b0, b1, b2, b3;
                ldsm_x4(b0, b1, b2, b3,
                    sKst + (uint32_t)((ntp * 16 + lb_row) * FA_STR + ks * 16 + lb_kk) * 2);
                mma_f16(sacc[2 * ntp],     a0, a1, a2, a3, b0, b1);
                mma_f16(sacc[2 * ntp + 1], a0, a1, a2, a3, b2, b3);
            }
        }
        // + attn_bias
        {
            const float* bp = abias + (size_t)(qrow0 + wq0) * LSEQ + kt * 64;
            #pragma unroll
            for (int nt = 0; nt < 8; nt++) {
                float2 b01 = *(const float2*)(bp + (size_t)gid * LSEQ + nt * 8 + 2 * tig);
                float2 b23 = *(const float2*)(bp + (size_t)(gid + 8) * LSEQ + nt * 8 + 2 * tig);
                sacc[nt][0] += b01.x; sacc[nt][1] += b01.y;
                sacc[nt][2] += b23.x; sacc[nt][3] += b23.y;
            }
        }
        // online softmax (rows gid and gid+8)
        float mx0 = -1e30f, mx1 = -1e30f;
        #pragma unroll
        for (int nt = 0; nt < 8; nt++) {
            mx0 = fmaxf(mx0, fmaxf(sacc[nt][0], sacc[nt][1]));
            mx1 = fmaxf(mx1, fmaxf(sacc[nt][2], sacc[nt][3]));
        }
        mx0 = fmaxf(mx0, __shfl_xor_sync(0xffffffffu, mx0, 1));
        mx0 = fmaxf(mx0, __shfl_xor_sync(0xffffffffu, mx0, 2));
        mx1 = fmaxf(mx1, __shfl_xor_sync(0xffffffffu, mx1, 1));
        mx1 = fmaxf(mx1, __shfl_xor_sync(0xffffffffu, mx1, 2));
        float mn0 = fmaxf(m0r, mx0), mn1 = fmaxf(m1r, mx1);
        float al0 = fexp(m0r - mn0), al1 = fexp(m1r - mn1);
        float rs0 = 0.f, rs1 = 0.f;
        #pragma unroll
        for (int nt = 0; nt < 8; nt++) {
            sacc[nt][0] = fexp(sacc[nt][0] - mn0);
            sacc[nt][1] = fexp(sacc[nt][1] - mn0);
            sacc[nt][2] = fexp(sacc[nt][2] - mn1);
            sacc[nt][3] = fexp(sacc[nt][3] - mn1);
            rs0 += sacc[nt][0] + sacc[nt][1];
            rs1 += sacc[nt][2] + sacc[nt][3];
        }
        rs0 += __shfl_xor_sync(0xffffffffu, rs0, 1);
        rs0 += __shfl_xor_sync(0xffffffffu, rs0, 2);
        rs1 += __shfl_xor_sync(0xffffffffu, rs1, 1);
        rs1 += __shfl_xor_sync(0xffffffffu, rs1, 2);
        l0 = l0 * al0 + rs0; l1 = l1 * al1 + rs1;
        m0r = mn0; m1r = mn1;
        #pragma unroll
        for (int dt = 0; dt < 8; dt++) {
            oacc[dt][0] *= al0; oacc[dt][1] *= al0;
            oacc[dt][2] *= al1; oacc[dt][3] *= al1;
        }
        // O += P V : A fragments chained directly from sacc; B = ldmatrix.trans on natural V
        #pragma unroll
        for (int kc = 0; kc < 4; kc++) {
            uint32_t a0 = f2h2(sacc[2 * kc][0],     sacc[2 * kc][1]);
            uint32_t a1 = f2h2(sacc[2 * kc][2],     sacc[2 * kc][3]);
            uint32_t a2 = f2h2(sacc[2 * kc + 1][0], sacc[2 * kc + 1][1]);
            uint32_t a3 = f2h2(sacc[2 * kc + 1][2], sacc[2 * kc + 1][3]);
            #pragma unroll
            for (int dtp = 0; dtp < 4; dtp++) {
                uint32_t b0, b1, b2, b3;
                int row = kc * 16 + lb_kk + (lane & 7);          // kcol rows (bit3 -> +8 row)
                int dcol = dtp * 16 + ((lane >> 4) & 1) * 8;     // d column (bit4 -> +8 col)
                ldsm_x4_t(b0, b1, b2, b3,
                    sVst + (uint32_t)(row * FA_STR + dcol) * 2);
                mma_f16(oacc[2 * dtp],     a0, a1, a2, a3, b0, b1);
                mma_f16(oacc[2 * dtp + 1], a0, a1, a2, a3, b2, b3);
            }
        }
    }
    // write O / l  (half) to [B*L, C]
    {
        float inv0 = 1.f / l0, inv1 = 1.f / l1;
        const size_t r0 = (size_t)(b * LSEQ + qrow0 + wq0 + gid);
        const size_t r1 = r0 + 8;
        #pragma unroll
        for (int dt = 0; dt < 8; dt++) {
            int col = h * DHD + dt * 8 + 2 * tig;
            *(uint32_t*)(out + r0 * CDIM + col) = f2h2(oacc[dt][0] * inv0, oacc[dt][1] * inv0);
            *(uint32_t*)(out + r1 * CDIM + col) = f2h2(oacc[dt][2] * inv1, oacc[dt][3] * inv1);
        }
    }
}

// ---------------- launch ----------------
extern "C" void kernel_launch(void* const* d_in, const int* in_sizes, int n_in,
                              void* d_out, int out_size)
{
    const float* x         = (const float*)d_in[0];
    const float* cond_BD   = (const float*)d_in[1];
    const float* attn_bias = (const float*)d_in[2];
    const float* qkv_w     = (const float*)d_in[3];
    const float* q_bias    = (const float*)d_in[4];
    const float* v_bias    = (const float*)d_in[5];
    const float* scale_mul = (const float*)d_in[6];
    const float* proj_w    = (const float*)d_in[7];
    const float* proj_b    = (const float*)d_in[8];
    const float* fc1_w     = (const float*)d_in[9];
    const float* fc1_b     = (const float*)d_in[10];
    const float* fc2_w     = (const float*)d_in[11];
    const float* fc2_b     = (const float*)d_in[12];
    const float* ada_w     = (const float*)d_in[13];
    const float* ada_b     = (const float*)d_in[14];
    float* outp = (float*)d_out;

    float *p_qkv, *p_x1;
    __half *p_wh, *p_hh, *p_qkvh, *p_attnh, *p_ffh;
    cudaGetSymbolAddress((void**)&p_qkv, g_qkv);
    cudaGetSymbolAddress((void**)&p_x1, g_x1);
    cudaGetSymbolAddress((void**)&p_wh, g_wh);
    cudaGetSymbolAddress((void**)&p_hh, g_hh);
    cudaGetSymbolAddress((void**)&p_qkvh, g_qkvh);
    cudaGetSymbolAddress((void**)&p_attnh, g_attnh);
    cudaGetSymbolAddress((void**)&p_ffh, g_ffh);

    cudaFuncSetAttribute(tc_gemm, cudaFuncAttributeMaxDynamicSharedMemorySize, TC_SMEM);
    cudaFuncSetAttribute(flash_mma, cudaFuncAttributeMaxDynamicSharedMemorySize, FA_SMEM);

    // 0) weight conversions (f32 -> f16)
    f2h_kernel<<<(3*CDIM*CDIM/4 + 255)/256, 256>>>((const float4*)qkv_w, (uint2*)(p_wh + WH_QKV), 3*CDIM*CDIM/4);
    f2h_kernel<<<(CDIM*CDIM/4 + 255)/256, 256>>>((const float4*)proj_w, (uint2*)(p_wh + WH_PROJ), CDIM*CDIM/4);
    f2h_kernel<<<(DFF*CDIM/4 + 255)/256, 256>>>((const float4*)fc1_w, (uint2*)(p_wh + WH_FC1), DFF*CDIM/4);
    f2h_kernel<<<(CDIM*DFF/4 + 255)/256, 256>>>((const float4*)fc2_w, (uint2*)(p_wh + WH_FC2), CDIM*DFF/4);

    // 1) adaLN coefficients
    ada_kernel<<<dim3(6 * CDIM / 4, BATCH), 128>>>(cond_BD, ada_w, ada_b);
    // 2) h = LN(x)*(s1+1)+sh1   (chunks: g1=0,g2=1,s1=2,s2=3,sh1=4,sh2=5)
    ln_mod_kernel<<<NROWS, 256>>>(x, p_hh, 2, 4);
    // 3) qkv = h @ qkv_w^T  (f32 out)
    tc_gemm<<<dim3(3 * CDIM / 128, NROWS / 128), 256, TC_SMEM>>>(
        CDIM, 3 * CDIM, p_hh, p_wh + WH_QKV, nullptr, p_qkv, nullptr, -1, 0, 0);
    // 4) bias + per-head L2 norm + scale -> half
    qkv_norm_kernel<<<NROWS * 3 * HEADS / 8, 256>>>(q_bias, v_bias, scale_mul);
    // 5) attention (fp16 mma) -> half
    flash_mma<<<dim3(LSEQ / 128, BATCH * HEADS), 256, FA_SMEM>>>(attn_bias, p_attnh);
    // 6) x1 = x + (attn @ proj_w^T + proj_b) * g1  (f32 out)
    tc_gemm<<<dim3(CDIM / 128, NROWS / 128), 256, TC_SMEM>>>(
        CDIM, CDIM, p_attnh, p_wh + WH_PROJ, proj_b, p_x1, x, 0, 0, 0);
    // 7) h = LN(x1)*(s2+1)+sh2
    ln_mod_kernel<<<NROWS, 256>>>(p_x1, p_hh, 3, 5);
    // 8) ff = gelu(h @ fc1_w^T + fc1_b)  (half out)
    tc_gemm<<<dim3(DFF / 128, NROWS / 128), 256, TC_SMEM>>>(
        CDIM, DFF, p_hh, p_wh + WH_FC1, fc1_b, p_ffh, nullptr, -1, 1, 1);
    // 9) out = x1 + (ff @ fc2_w^T + fc2_b) * g2  (f32 out)
    tc_gemm<<<dim3(CDIM / 128, NROWS / 128), 256, TC_SMEM>>>(
        DFF, CDIM, p_ffh, p_wh + WH_FC2, fc2_b, outp, p_x1, 1, 0, 0);
}